// round 13
// baseline (speedup 1.0000x reference)
#include <cuda_runtime.h>
#include <cuda_fp16.h>
#include <cuda_bf16.h>
#include <cstdint>

// ---------------------------------------------------------------------------
// DeformableAttention (MSDA): B=8, C=256, H=8, d=32, Lv=4, P=4
//   wt_convert : transpose weights -> bf16 hi/lo [896,256] + fp16 [512,256]
//   split_mat  : query fp32 -> bf16 hi/lo ; split_f16: flat fp32 -> fp16
//   gemm_nt<3> : bf16 3-term-split GEMM (offsets/attn)
//   gemm_nt<1> : fp16 single-pass GEMM (value, output)
//   msda_sample: v4 head-major value, 128B pair loads (unchanged from r12)
// r13 vs r12: GEMM warp tile 32x64 -> 64x64 (CTA 256x128, 8 warps, 128 acc
//             regs, 1 CTA/SM). Cuts SMEM bytes per MMA 33% (LDS-bound fix).
// ---------------------------------------------------------------------------

#define MAXROWS 106496ull  // >= B*Nq = 8*13294, multiple of 256

__device__ __align__(16) __half         g_value_h[MAXROWS * 256];   // head-major
__device__ float                        g_offattn[MAXROWS * 384];
__device__ __align__(16) __half         g_f_h16[MAXROWS * 256];
__device__ __align__(16) __half         g_m_h16[MAXROWS * 256];
__device__ __align__(16) __nv_bfloat16  g_q_hi[MAXROWS * 256], g_q_lo[MAXROWS * 256];
__device__ __align__(16) __nv_bfloat16  g_wt_hi[896 * 256],    g_wt_lo[896 * 256];
__device__ __align__(16) __half         g_wt_h16[512 * 256];   // W_val^T, W_out^T

// ---- helpers ----------------------------------------------------------------
__device__ __forceinline__ uint32_t smem_u32(const void* p) {
    uint32_t a;
    asm("{ .reg .u64 t; cvta.to.shared.u64 t, %1; cvt.u32.u64 %0, t; }"
        : "=r"(a) : "l"(p));
    return a;
}
__device__ __forceinline__ void ldm_x4(uint32_t* r, uint32_t addr) {
    asm volatile("ldmatrix.sync.aligned.m8n8.x4.shared.b16 {%0,%1,%2,%3}, [%4];"
                 : "=r"(r[0]), "=r"(r[1]), "=r"(r[2]), "=r"(r[3]) : "r"(addr));
}
__device__ __forceinline__ void mma_bf16(float* d, const uint32_t* a,
                                         uint32_t b0, uint32_t b1) {
    asm volatile(
        "mma.sync.aligned.m16n8k16.row.col.f32.bf16.bf16.f32 "
        "{%0,%1,%2,%3}, {%4,%5,%6,%7}, {%8,%9}, {%0,%1,%2,%3};"
        : "+f"(d[0]), "+f"(d[1]), "+f"(d[2]), "+f"(d[3])
        : "r"(a[0]), "r"(a[1]), "r"(a[2]), "r"(a[3]), "r"(b0), "r"(b1));
}
__device__ __forceinline__ void mma_f16(float* d, const uint32_t* a,
                                        uint32_t b0, uint32_t b1) {
    asm volatile(
        "mma.sync.aligned.m16n8k16.row.col.f32.f16.f16.f32 "
        "{%0,%1,%2,%3}, {%4,%5,%6,%7}, {%8,%9}, {%0,%1,%2,%3};"
        : "+f"(d[0]), "+f"(d[1]), "+f"(d[2]), "+f"(d[3])
        : "r"(a[0]), "r"(a[1]), "r"(a[2]), "r"(a[3]), "r"(b0), "r"(b1));
}
#define CP16(dst, src)                                                        \
    asm volatile("cp.async.cg.shared.global [%0], [%1], 16;"                  \
                 :: "r"(dst), "l"(src) : "memory")
#define CP_COMMIT() asm volatile("cp.async.commit_group;" ::: "memory")
#define CP_WAIT1()  asm volatile("cp.async.wait_group 1;" ::: "memory")
#define CP_WAIT0()  asm volatile("cp.async.wait_group 0;" ::: "memory")

// ---- weight pre-transpose + split --------------------------------------------
__global__ void wt_convert(const float* __restrict__ Wv, const float* __restrict__ Wo,
                           const float* __restrict__ Wa, const float* __restrict__ Wu) {
    int idx = blockIdx.x * 256 + threadIdx.x;   // 896*256 total
    if (idx >= 896 * 256) return;
    int n = idx >> 8, k = idx & 255;
    float v;
    if      (n < 256) v = Wv[k * 256 + n];
    else if (n < 512) v = Wo[k * 256 + (n - 256)];
    else if (n < 640) v = Wa[k * 128 + (n - 512)];
    else              v = Wu[k * 256 + (n - 640)];
    __nv_bfloat16 hi = __float2bfloat16(v);
    __nv_bfloat16 lo = __float2bfloat16(v - __bfloat162float(hi));
    g_wt_hi[n * 256 + k] = hi;
    g_wt_lo[n * 256 + k] = lo;
    if (n < 256)       g_wt_h16[n * 256 + k]               = __float2half(v);
    else if (n >= 640) g_wt_h16[(n - 640 + 256) * 256 + k] = __float2half(v);
}

// ---- query split: fp32 [M,256] -> bf16 hi/lo, zero pad rows ------------------
__global__ __launch_bounds__(256) void split_mat(
    const float* __restrict__ src, __nv_bfloat16* __restrict__ hi,
    __nv_bfloat16* __restrict__ lo, int nquad)
{
    const int idx = blockIdx.x * 256 + threadIdx.x;
    if (idx >= (int)(MAXROWS * 64)) return;
    float4 v = make_float4(0.f, 0.f, 0.f, 0.f);
    if (idx < nquad) v = ((const float4*)src)[idx];
    __nv_bfloat16 h0 = __float2bfloat16(v.x), h1 = __float2bfloat16(v.y);
    __nv_bfloat16 h2 = __float2bfloat16(v.z), h3 = __float2bfloat16(v.w);
    __nv_bfloat162 ph0(h0, h1), ph1(h2, h3);
    __nv_bfloat162 pl0(__float2bfloat16(v.x - __bfloat162float(h0)),
                       __float2bfloat16(v.y - __bfloat162float(h1)));
    __nv_bfloat162 pl1(__float2bfloat16(v.z - __bfloat162float(h2)),
                       __float2bfloat16(v.w - __bfloat162float(h3)));
    uint2 uh, ul;
    uh.x = *(uint32_t*)&ph0; uh.y = *(uint32_t*)&ph1;
    ul.x = *(uint32_t*)&pl0; ul.y = *(uint32_t*)&pl1;
    *(uint2*)(hi + (size_t)idx * 4) = uh;
    *(uint2*)(lo + (size_t)idx * 4) = ul;
}

// ---- flat convert: fp32 -> fp16, zero pad rows -------------------------------
__global__ __launch_bounds__(256) void split_f16(
    const float* __restrict__ src, __half* __restrict__ dst, int nquad)
{
    const int idx = blockIdx.x * 256 + threadIdx.x;
    if (idx >= (int)(MAXROWS * 64)) return;
    float4 v = make_float4(0.f, 0.f, 0.f, 0.f);
    if (idx < nquad) v = ((const float4*)src)[idx];
    __half2 a = __floats2half2_rn(v.x, v.y);
    __half2 b = __floats2half2_rn(v.z, v.w);
    uint2 u;
    u.x = *(uint32_t*)&a; u.y = *(uint32_t*)&b;
    *(uint2*)(dst + (size_t)idx * 4) = u;
}

// ---- mma.sync GEMM: CTA 256x128, 8 warps x (64m x 64n), 128 acc regs --------
// NT==3: bf16 3-term split (single SMEM stage).
// NT==1: fp16 single-pass (2-stage cp.async pipeline, same SMEM footprint).
// C[M,N] = A[M,256] @ B^T + bias ; bias routed at col nsplit.
// outhalf==1: fp16 HEAD-MAJOR value store [b][h][pos][32] (needs Ltot).
#define RS 72
#define ATILE (256 * RS * 2)           // 36864 B
#define BTILE (128 * RS * 2)           // 18432 B
#define STG_NT1 (ATILE + BTILE)        // 55296 B
#define SM_GEMM (2 * ATILE + 2 * BTILE) // 110592 B (NT3 1-stage / NT1 2-stage)

template <int NT>
__global__ __launch_bounds__(256, 1) void gemm_nt(
    const __nv_bfloat16* __restrict__ Ah, const __nv_bfloat16* __restrict__ Al,
    const __nv_bfloat16* __restrict__ Bh, const __nv_bfloat16* __restrict__ Bl,
    const float* __restrict__ bias1, const float* __restrict__ bias2,
    int nsplit, void* __restrict__ Cout, int ldc, int M, int N, int outhalf,
    int Ltot)
{
    extern __shared__ char smem[];
    const uint32_t sb = smem_u32(smem);
    const int tid  = threadIdx.x;
    const int lane = tid & 31;
    const int wid  = tid >> 5;
    const int wm   = wid >> 1;       // m-group: rows wm*64..+63
    const int wn   = wid & 1;        // n-group: cols wn*64..+63
    const int bm   = blockIdx.y * 256;
    const int bn   = blockIdx.x * 128;

    auto load_chunk = [&](int c) {
        const uint32_t st = (NT == 1) ? sb + (uint32_t)((c & 1) * STG_NT1) : sb;
        const uint32_t bhoff = (NT == 3) ? 2u * ATILE : (uint32_t)ATILE;
        const int kb = c * 64;
#pragma unroll
        for (int i = 0; i < 8; i++) {                 // A: 256 rows
            const int idx = tid + i * 256;
            const int row = idx >> 3, gk = idx & 7;
            const uint32_t doff = (uint32_t)((row * RS + gk * 8) * 2);
            const size_t asrc = (size_t)(bm + row) * 256 + kb + gk * 8;
            CP16(st + doff, Ah + asrc);
            if (NT == 3) CP16(st + ATILE + doff, Al + asrc);
        }
#pragma unroll
        for (int i = 0; i < 4; i++) {                 // B: 128 rows
            const int idx = tid + i * 256;
            const int row = idx >> 3, gk = idx & 7;
            const uint32_t doff = (uint32_t)((row * RS + gk * 8) * 2);
            const size_t bsrc = (size_t)(bn + row) * 256 + kb + gk * 8;
            CP16(st + bhoff + doff, Bh + bsrc);
            if (NT == 3) CP16(st + bhoff + BTILE + doff, Bl + bsrc);
        }
        CP_COMMIT();
    };

    float acc[4][8][4];
#pragma unroll
    for (int mi = 0; mi < 4; mi++)
#pragma unroll
        for (int j = 0; j < 8; j++)
#pragma unroll
            for (int q = 0; q < 4; q++) acc[mi][j][q] = 0.f;

    const int fr = lane & 15;
    const int fc = (lane >> 4) << 3;
    const uint32_t aoff = (uint32_t)(((wm * 64 + fr) * RS + fc) * 2);
    const uint32_t boff = (uint32_t)(((wn * 64 + fr) * RS + fc) * 2);

    if (NT == 1) load_chunk(0);

    for (int c = 0; c < 4; c++) {
        if (NT == 1) {
            if (c < 3) { load_chunk(c + 1); CP_WAIT1(); }
            else       { CP_WAIT0(); }
        } else {
            load_chunk(c);
            CP_WAIT0();
        }
        __syncthreads();

        const uint32_t st  = (NT == 1) ? sb + (uint32_t)((c & 1) * STG_NT1) : sb;
        const uint32_t sAh = st;
        const uint32_t sAl = st + ATILE;                          // NT3 only
        const uint32_t sBh = st + ((NT == 3) ? 2u * ATILE : (uint32_t)ATILE);
        const uint32_t sBl = sBh + BTILE;                         // NT3 only

#pragma unroll
        for (int ks = 0; ks < 4; ks++) {
            const uint32_t kadd = (uint32_t)(ks * 16 * 2);
            uint32_t ahf[4][4], alf[4][4], bhf[4][4], blf[4][4];
#pragma unroll
            for (int mi = 0; mi < 4; mi++) {
                const uint32_t ao = aoff + (uint32_t)(mi * 16 * RS * 2) + kadd;
                ldm_x4(ahf[mi], sAh + ao);
                if (NT == 3) ldm_x4(alf[mi], sAl + ao);
            }
#pragma unroll
            for (int jj = 0; jj < 4; jj++) {
                const uint32_t bo = boff + (uint32_t)(jj * 16 * RS * 2) + kadd;
                ldm_x4(bhf[jj], sBh + bo);
                if (NT == 3) ldm_x4(blf[jj], sBl + bo);
            }
#pragma unroll
            for (int mi = 0; mi < 4; mi++)
#pragma unroll
                for (int j = 0; j < 8; j++) {
                    const int jj = j >> 1, sel = j & 1;
                    const uint32_t b0h = bhf[jj][sel], b1h = bhf[jj][sel + 2];
                    if (NT == 3) {
                        const uint32_t b0l = blf[jj][sel], b1l = blf[jj][sel + 2];
                        mma_bf16(acc[mi][j], ahf[mi], b0h, b1h);
                        mma_bf16(acc[mi][j], ahf[mi], b0l, b1l);
                        mma_bf16(acc[mi][j], alf[mi], b0h, b1h);
                    } else {
                        mma_f16(acc[mi][j], ahf[mi], b0h, b1h);
                    }
                }
        }
        __syncthreads();
    }

    // ---- epilogue ----
    const int gcol0 = bn + wn * 64;
    const float* bp = bias1;
    int cb = 0;
    if (gcol0 >= nsplit) { bp = bias2; cb = nsplit; }

    const int rq = lane >> 2;
    const int cq = (lane & 3) * 2;

    if (outhalf) {
        // head-major fp16 store: [b][h][pos][32]
        __half* Ch = (__half*)Cout;
        int rr[8], bb[8], pp[8];
#pragma unroll
        for (int r = 0; r < 8; r++) {
            rr[r] = bm + wm * 64 + (r >> 1) * 16 + (r & 1) * 8 + rq;
            bb[r] = rr[r] / Ltot;
            pp[r] = rr[r] - bb[r] * Ltot;
        }
#pragma unroll
        for (int mi = 0; mi < 4; mi++) {
#pragma unroll
            for (int j = 0; j < 8; j++) {
                const int col = gcol0 + j * 8 + cq;
                const float2 bv = *(const float2*)(bp + (col - cb));
                const int h  = col >> 5;
                const int ch = col & 31;
#pragma unroll
                for (int half2i = 0; half2i < 2; half2i++) {
                    const int r = mi * 2 + half2i;
                    if (rr[r] < M) {
                        const size_t o =
                            ((size_t)(bb[r] * 8 + h) * Ltot + pp[r]) * 32 + ch;
                        *(__half2*)(Ch + o) = __floats2half2_rn(
                            acc[mi][j][half2i * 2 + 0] + bv.x,
                            acc[mi][j][half2i * 2 + 1] + bv.y);
                    }
                }
            }
        }
    } else {
        float* Cf = (float*)Cout;
#pragma unroll
        for (int mi = 0; mi < 4; mi++) {
#pragma unroll
            for (int j = 0; j < 8; j++) {
                const int col = gcol0 + j * 8 + cq;
                const float2 bv = *(const float2*)(bp + (col - cb));
                const int row0 = bm + wm * 64 + mi * 16 + rq;
                if (row0 < M)
                    *(float2*)(Cf + (size_t)row0 * ldc + col) =
                        make_float2(acc[mi][j][0] + bv.x, acc[mi][j][1] + bv.y);
                if (row0 + 8 < M)
                    *(float2*)(Cf + (size_t)(row0 + 8) * ldc + col) =
                        make_float2(acc[mi][j][2] + bv.x, acc[mi][j][3] + bv.y);
            }
        }
    }
}

// ---- sampler v4: 4 heads/warp, head-major value, 128B pair loads ------------
__global__ __launch_bounds__(256) void msda_sample_v4(
    const float* __restrict__ rp, const int* __restrict__ shapes, int M)
{
    __shared__ int s_w[4], s_h[4], s_start[4];
    __shared__ float s_fw[4], s_fh[4];
    __shared__ int s_L;
    if (threadIdx.x == 0) {
        int st = 0;
        for (int l = 0; l < 4; l++) {
            int hh = shapes[2 * l], ww = shapes[2 * l + 1];
            s_h[l] = hh; s_w[l] = ww; s_start[l] = st;
            s_fh[l] = (float)hh; s_fw[l] = (float)ww;
            st += hh * ww;
        }
        s_L = st;
    }
    __syncthreads();
    const int Ltot = s_L;

    const unsigned FULL = 0xffffffffu;
    const int lane = threadIdx.x & 31;
    const int warp = threadIdx.x >> 5;
    const int t = blockIdx.x * 4 + (warp >> 1);
    if (t >= M) return;
    const int h   = (warp & 1) * 4 + (lane >> 3);
    const int sub = lane & 7;
    const int b   = t / Ltot;

    float logit0, logit1;
    int   pi[2], pst[2];
    float pc00[2], pc10[2], pc01[2], pc11[2];
    {
        const float* ab = g_offattn + (size_t)t * 384 + 256 + h * 16;
        logit0 = ab[sub * 2];
        logit1 = ab[sub * 2 + 1];
    }
    float mx = fmaxf(logit0, logit1);
#pragma unroll
    for (int s = 4; s; s >>= 1) mx = fmaxf(mx, __shfl_xor_sync(FULL, mx, s));
    float e0 = expf(logit0 - mx), e1 = expf(logit1 - mx);
    float sm = e0 + e1;
#pragma unroll
    for (int s = 4; s; s >>= 1) sm += __shfl_xor_sync(FULL, sm, s);
    const float inv = 1.f / sm;

#pragma unroll
    for (int s = 0; s < 2; s++) {
        const int pt = sub * 2 + s;
        const int l  = pt >> 2;
        const float aw = (s ? e1 : e0) * inv;
        float2 off = *(const float2*)(g_offattn + (size_t)t * 384 + h * 32 + pt * 2);
        float2 ref = *(const float2*)(rp + (size_t)t * 8 + l * 2);
        const int w_ = s_w[l], h_ = s_h[l];
        const float x = (ref.x + off.x) * s_fw[l] - 0.5f;
        const float y = (ref.y + off.y) * s_fh[l] - 0.5f;
        const float x0f = floorf(x), y0f = floorf(y);
        const float fx = x - x0f, fy = y - y0f;
        const int x0 = (int)x0f, y0 = (int)y0f;
        const float m00 = ((x0 >= 0)     & (x0 < w_)     & (y0 >= 0)     & (y0 < h_))     ? 1.f : 0.f;
        const float m10 = ((x0 + 1 >= 0) & (x0 + 1 < w_) & (y0 >= 0)     & (y0 < h_))     ? 1.f : 0.f;
        const float m01 = ((x0 >= 0)     & (x0 < w_)     & (y0 + 1 >= 0) & (y0 + 1 < h_)) ? 1.f : 0.f;
        const float m11 = ((x0 + 1 >= 0) & (x0 + 1 < w_) & (y0 + 1 >= 0) & (y0 + 1 < h_)) ? 1.f : 0.f;
        const int xc0 = min(max(x0, 0), w_ - 1);
        const int xc1 = min(max(x0 + 1, 0), w_ - 1);
        const int yc0 = min(max(y0, 0), h_ - 1);
        const int yc1 = min(max(y0 + 1, 0), h_ - 1);
        pi[s]  = s_start[l] + yc0 * w_ + xc0;
        pst[s] = (xc1 - xc0) | ((yc1 - yc0) * w_ << 16);
        const float gx1 = fx, gx0 = 1.f - fx;
        const float gy1 = fy, gy0 = 1.f - fy;
        pc00[s] = gx0 * gy0 * m00 * aw;
        pc10[s] = gx1 * gy0 * m10 * aw;
        pc01[s] = gx0 * gy1 * m01 * aw;
        pc11[s] = gx1 * gy1 * m11 * aw;
    }

    const int hi4 = sub >> 2;
    const int q4  = sub & 3;
    const uint4* vb = (const uint4*)g_value_h
                    + ((size_t)(b * 8 + h) * Ltot) * 4 + q4;
    float a8[8];
#pragma unroll
    for (int k = 0; k < 8; k++) a8[k] = 0.f;

#pragma unroll
    for (int pt = 0; pt < 16; pt++) {
        const int src  = pt >> 1;
        const int slot = pt & 1;
        const int   i00 = slot ? __shfl_sync(FULL, pi[1],   src, 8) : __shfl_sync(FULL, pi[0],   src, 8);
        const int   st  = slot ? __shfl_sync(FULL, pst[1],  src, 8) : __shfl_sync(FULL, pst[0],  src, 8);
        const float c00 = slot ? __shfl_sync(FULL, pc00[1], src, 8) : __shfl_sync(FULL, pc00[0], src, 8);
        const float c10 = slot ? __shfl_sync(FULL, pc10[1], src, 8) : __shfl_sync(FULL, pc10[0], src, 8);
        const float c01 = slot ? __shfl_sync(FULL, pc01[1], src, 8) : __shfl_sync(FULL, pc01[0], src, 8);
        const float c11 = slot ? __shfl_sync(FULL, pc11[1], src, 8) : __shfl_sync(FULL, pc11[0], src, 8);
        const int cs = st & 0xffff;
        const int rs = st >> 16;
        const int addsel = hi4 ? cs : 0;
        const uint4 uA = vb[(size_t)(i00 + addsel) * 4];
        const uint4 uB = vb[(size_t)(i00 + rs + addsel) * 4];
        const float cA = hi4 ? c10 : c00;
        const float cB = hi4 ? c11 : c01;
#define ACC8(u, cc)                                                            \
        {                                                                      \
            float2 f0 = __half22float2(*(const __half2*)&(u).x);               \
            float2 f1 = __half22float2(*(const __half2*)&(u).y);               \
            float2 f2 = __half22float2(*(const __half2*)&(u).z);               \
            float2 f3 = __half22float2(*(const __half2*)&(u).w);               \
            a8[0] = fmaf(cc, f0.x, a8[0]); a8[1] = fmaf(cc, f0.y, a8[1]);      \
            a8[2] = fmaf(cc, f1.x, a8[2]); a8[3] = fmaf(cc, f1.y, a8[3]);      \
            a8[4] = fmaf(cc, f2.x, a8[4]); a8[5] = fmaf(cc, f2.y, a8[5]);      \
            a8[6] = fmaf(cc, f3.x, a8[6]); a8[7] = fmaf(cc, f3.y, a8[7]);      \
        }
        ACC8(uA, cA) ACC8(uB, cB)
#undef ACC8
    }

#pragma unroll
    for (int k = 0; k < 8; k++)
        a8[k] += __shfl_xor_sync(FULL, a8[k], 4);

    if (hi4 == 0) {
        __half2 o0 = __floats2half2_rn(a8[0], a8[1]);
        __half2 o1 = __floats2half2_rn(a8[2], a8[3]);
        __half2 o2 = __floats2half2_rn(a8[4], a8[5]);
        __half2 o3 = __floats2half2_rn(a8[6], a8[7]);
        uint4 u;
        u.x = *(uint32_t*)&o0; u.y = *(uint32_t*)&o1;
        u.z = *(uint32_t*)&o2; u.w = *(uint32_t*)&o3;
        *(uint4*)(g_m_h16 + (size_t)t * 256 + h * 32 + q4 * 8) = u;
    }
}

// ---------------------------------------------------------------------------
extern "C" void kernel_launch(void* const* d_in, const int* in_sizes, int n_in,
                              void* d_out, int out_size)
{
    const float* query   = (const float*)d_in[0];
    const float* rp      = (const float*)d_in[1];
    const float* flat    = (const float*)d_in[2];
    const int*   shapes  = (const int*)  d_in[3];
    const float* W_off   = (const float*)d_in[4];
    const float* b_off   = (const float*)d_in[5];
    const float* W_attn  = (const float*)d_in[6];
    const float* b_attn  = (const float*)d_in[7];
    const float* W_val   = (const float*)d_in[8];
    const float* b_val   = (const float*)d_in[9];
    const float* W_out   = (const float*)d_in[10];
    const float* b_out   = (const float*)d_in[11];
    float* out = (float*)d_out;

    const int M = in_sizes[0] / 256;
    const int Ltot = M / 8;            // B = 8

    void *pvh, *poa, *pf16, *pm16, *pqh, *pql, *pwh, *pwl, *pw16;
    cudaGetSymbolAddress(&pvh, g_value_h);
    cudaGetSymbolAddress(&poa, g_offattn);
    cudaGetSymbolAddress(&pf16, g_f_h16);
    cudaGetSymbolAddress(&pm16, g_m_h16);
    cudaGetSymbolAddress(&pqh, g_q_hi); cudaGetSymbolAddress(&pql, g_q_lo);
    cudaGetSymbolAddress(&pwh, g_wt_hi); cudaGetSymbolAddress(&pwl, g_wt_lo);
    cudaGetSymbolAddress(&pw16, g_wt_h16);

    cudaFuncSetAttribute(gemm_nt<3>, cudaFuncAttributeMaxDynamicSharedMemorySize,
                         SM_GEMM);
    cudaFuncSetAttribute(gemm_nt<1>, cudaFuncAttributeMaxDynamicSharedMemorySize,
                         SM_GEMM);

    const int mtiles = (M + 255) / 256;
    const int splitg = (int)(MAXROWS * 64 / 256);

    const __nv_bfloat16* wh  = (const __nv_bfloat16*)pwh;
    const __nv_bfloat16* wl  = (const __nv_bfloat16*)pwl;
    const __half*        w16 = (const __half*)pw16;

    wt_convert<<<896, 256>>>(W_val, W_off, W_attn, W_out);
    split_f16<<<splitg, 256>>>(flat, (__half*)pf16, M * 64);
    split_mat<<<splitg, 256>>>(query, (__nv_bfloat16*)pqh, (__nv_bfloat16*)pql, M * 64);

    // GEMM1: value projection, fp16 single-pass -> fp16 HEAD-MAJOR
    gemm_nt<1><<<dim3(2, mtiles), 256, SM_GEMM>>>(
        (const __nv_bfloat16*)pf16, nullptr,
        (const __nv_bfloat16*)w16, nullptr,
        b_val, b_val, 256, pvh, 256, M, 256, 1, Ltot);
    // GEMM2: fused offsets+attn, 3-term bf16 -> fp32
    gemm_nt<3><<<dim3(3, mtiles), 256, SM_GEMM>>>(
        (const __nv_bfloat16*)pqh, (const __nv_bfloat16*)pql,
        wh + 256 * 256, wl + 256 * 256,
        b_off, b_attn, 256, poa, 384, M, 384, 0, Ltot);

    msda_sample_v4<<<dim3((M + 3) / 4), 256>>>(rp, shapes, M);

    // GEMM3: output projection, fp16 single-pass -> fp32 (d_out)
    gemm_nt<1><<<dim3(2, mtiles), 256, SM_GEMM>>>(
        (const __nv_bfloat16*)pm16, nullptr,
        (const __nv_bfloat16*)(w16 + 256 * 256), nullptr,
        b_out, b_out, 256, out, 256, M, 256, 0, Ltot);
}

// round 14
// speedup vs baseline: 1.0958x; 1.0958x over previous
#include <cuda_runtime.h>
#include <cuda_fp16.h>
#include <cuda_bf16.h>
#include <cstdint>

// ---------------------------------------------------------------------------
// DeformableAttention (MSDA): B=8, C=256, H=8, d=32, Lv=4, P=4
//   wt_convert : transpose weights -> bf16 hi/lo [896,256] + fp16 [512,256]
//   split_mat  : query fp32 -> bf16 hi/lo ; split_f16: flat fp32 -> fp16
//   gemm_nt<3> : bf16 3-term-split GEMM (offsets/attn), 128x128 CTA, 2 CTA/SM
//   gemm_nt<1> : fp16 single-pass GEMM (value, output), 2-stage cp.async
//   msda_sample: v5 -- head-major value pair loads + half2-packed coefficient
//                shuffles (4 shfl/point instead of 6)
// r14 vs r13: GEMM reverted to r12 (128x128, 2 CTA/SM; r13 64x64 regressed);
//             sampler shuffle count cut via half2 coefficient packing.
// ---------------------------------------------------------------------------

#define MAXROWS 106496ull  // >= B*Nq = 8*13294, padded to 128

__device__ __align__(16) __half         g_value_h[MAXROWS * 256];   // head-major
__device__ float                        g_offattn[MAXROWS * 384];
__device__ __align__(16) __half         g_f_h16[MAXROWS * 256];
__device__ __align__(16) __half         g_m_h16[MAXROWS * 256];
__device__ __align__(16) __nv_bfloat16  g_q_hi[MAXROWS * 256], g_q_lo[MAXROWS * 256];
__device__ __align__(16) __nv_bfloat16  g_wt_hi[896 * 256],    g_wt_lo[896 * 256];
__device__ __align__(16) __half         g_wt_h16[512 * 256];   // W_val^T, W_out^T

// ---- helpers ----------------------------------------------------------------
__device__ __forceinline__ uint32_t smem_u32(const void* p) {
    uint32_t a;
    asm("{ .reg .u64 t; cvta.to.shared.u64 t, %1; cvt.u32.u64 %0, t; }"
        : "=r"(a) : "l"(p));
    return a;
}
__device__ __forceinline__ void ldm_x4(uint32_t* r, uint32_t addr) {
    asm volatile("ldmatrix.sync.aligned.m8n8.x4.shared.b16 {%0,%1,%2,%3}, [%4];"
                 : "=r"(r[0]), "=r"(r[1]), "=r"(r[2]), "=r"(r[3]) : "r"(addr));
}
__device__ __forceinline__ void mma_bf16(float* d, const uint32_t* a,
                                         uint32_t b0, uint32_t b1) {
    asm volatile(
        "mma.sync.aligned.m16n8k16.row.col.f32.bf16.bf16.f32 "
        "{%0,%1,%2,%3}, {%4,%5,%6,%7}, {%8,%9}, {%0,%1,%2,%3};"
        : "+f"(d[0]), "+f"(d[1]), "+f"(d[2]), "+f"(d[3])
        : "r"(a[0]), "r"(a[1]), "r"(a[2]), "r"(a[3]), "r"(b0), "r"(b1));
}
__device__ __forceinline__ void mma_f16(float* d, const uint32_t* a,
                                        uint32_t b0, uint32_t b1) {
    asm volatile(
        "mma.sync.aligned.m16n8k16.row.col.f32.f16.f16.f32 "
        "{%0,%1,%2,%3}, {%4,%5,%6,%7}, {%8,%9}, {%0,%1,%2,%3};"
        : "+f"(d[0]), "+f"(d[1]), "+f"(d[2]), "+f"(d[3])
        : "r"(a[0]), "r"(a[1]), "r"(a[2]), "r"(a[3]), "r"(b0), "r"(b1));
}
#define CP16(dst, src)                                                        \
    asm volatile("cp.async.cg.shared.global [%0], [%1], 16;"                  \
                 :: "r"(dst), "l"(src) : "memory")
#define CP_COMMIT() asm volatile("cp.async.commit_group;" ::: "memory")
#define CP_WAIT1()  asm volatile("cp.async.wait_group 1;" ::: "memory")
#define CP_WAIT0()  asm volatile("cp.async.wait_group 0;" ::: "memory")

// ---- weight pre-transpose + split --------------------------------------------
__global__ void wt_convert(const float* __restrict__ Wv, const float* __restrict__ Wo,
                           const float* __restrict__ Wa, const float* __restrict__ Wu) {
    int idx = blockIdx.x * 256 + threadIdx.x;   // 896*256 total
    if (idx >= 896 * 256) return;
    int n = idx >> 8, k = idx & 255;
    float v;
    if      (n < 256) v = Wv[k * 256 + n];
    else if (n < 512) v = Wo[k * 256 + (n - 256)];
    else if (n < 640) v = Wa[k * 128 + (n - 512)];
    else              v = Wu[k * 256 + (n - 640)];
    __nv_bfloat16 hi = __float2bfloat16(v);
    __nv_bfloat16 lo = __float2bfloat16(v - __bfloat162float(hi));
    g_wt_hi[n * 256 + k] = hi;
    g_wt_lo[n * 256 + k] = lo;
    if (n < 256)       g_wt_h16[n * 256 + k]               = __float2half(v);
    else if (n >= 640) g_wt_h16[(n - 640 + 256) * 256 + k] = __float2half(v);
}

// ---- query split: fp32 [M,256] -> bf16 hi/lo, zero pad rows ------------------
__global__ __launch_bounds__(256) void split_mat(
    const float* __restrict__ src, __nv_bfloat16* __restrict__ hi,
    __nv_bfloat16* __restrict__ lo, int nquad)
{
    const int idx = blockIdx.x * 256 + threadIdx.x;
    if (idx >= (int)(MAXROWS * 64)) return;
    float4 v = make_float4(0.f, 0.f, 0.f, 0.f);
    if (idx < nquad) v = ((const float4*)src)[idx];
    __nv_bfloat16 h0 = __float2bfloat16(v.x), h1 = __float2bfloat16(v.y);
    __nv_bfloat16 h2 = __float2bfloat16(v.z), h3 = __float2bfloat16(v.w);
    __nv_bfloat162 ph0(h0, h1), ph1(h2, h3);
    __nv_bfloat162 pl0(__float2bfloat16(v.x - __bfloat162float(h0)),
                       __float2bfloat16(v.y - __bfloat162float(h1)));
    __nv_bfloat162 pl1(__float2bfloat16(v.z - __bfloat162float(h2)),
                       __float2bfloat16(v.w - __bfloat162float(h3)));
    uint2 uh, ul;
    uh.x = *(uint32_t*)&ph0; uh.y = *(uint32_t*)&ph1;
    ul.x = *(uint32_t*)&pl0; ul.y = *(uint32_t*)&pl1;
    *(uint2*)(hi + (size_t)idx * 4) = uh;
    *(uint2*)(lo + (size_t)idx * 4) = ul;
}

// ---- flat convert: fp32 -> fp16, zero pad rows -------------------------------
__global__ __launch_bounds__(256) void split_f16(
    const float* __restrict__ src, __half* __restrict__ dst, int nquad)
{
    const int idx = blockIdx.x * 256 + threadIdx.x;
    if (idx >= (int)(MAXROWS * 64)) return;
    float4 v = make_float4(0.f, 0.f, 0.f, 0.f);
    if (idx < nquad) v = ((const float4*)src)[idx];
    __half2 a = __floats2half2_rn(v.x, v.y);
    __half2 b = __floats2half2_rn(v.z, v.w);
    uint2 u;
    u.x = *(uint32_t*)&a; u.y = *(uint32_t*)&b;
    *(uint2*)(dst + (size_t)idx * 4) = u;
}

// ---- templated mma.sync GEMM (r12 config: CTA 128x128, 2 CTAs/SM) -----------
// NT==3: bf16 3-term split, single stage.  NT==1: fp16 single, 2-stage pipeline.
// C[M,N] = A[M,256] @ B^T + bias ; bias routed at col nsplit.
// outhalf==1: fp16 HEAD-MAJOR value store [b][h][pos][32] (needs Ltot).
#define RS 72
#define TILE_B (128 * RS * 2)          // 18432 B
#define SM_GEMM (4 * TILE_B)           // 73728 B

template <int NT>
__global__ __launch_bounds__(256, 2) void gemm_nt(
    const __nv_bfloat16* __restrict__ Ah, const __nv_bfloat16* __restrict__ Al,
    const __nv_bfloat16* __restrict__ Bh, const __nv_bfloat16* __restrict__ Bl,
    const float* __restrict__ bias1, const float* __restrict__ bias2,
    int nsplit, void* __restrict__ Cout, int ldc, int M, int N, int outhalf,
    int Ltot)
{
    extern __shared__ char smem[];
    const uint32_t sb = smem_u32(smem);
    const int tid  = threadIdx.x;
    const int lane = tid & 31;
    const int wid  = tid >> 5;
    const int wm   = wid & 3;
    const int wn   = wid >> 2;
    const int bm   = blockIdx.y * 128;
    const int bn   = blockIdx.x * 128;

    auto load_chunk = [&](int c) {
        const uint32_t st = (NT == 1) ? sb + (uint32_t)((c & 1) * 2 * TILE_B) : sb;
        const int kb = c * 64;
#pragma unroll
        for (int i = 0; i < 4; i++) {
            const int idx = tid + i * 256;
            const int row = idx >> 3, gk = idx & 7;
            const uint32_t doff = (uint32_t)((row * RS + gk * 8) * 2);
            const size_t asrc = (size_t)(bm + row) * 256 + kb + gk * 8;
            const size_t bsrc = (size_t)(bn + row) * 256 + kb + gk * 8;
            CP16(st + doff, Ah + asrc);
            if (NT == 3) CP16(st + TILE_B + doff, Al + asrc);
            CP16(st + ((NT == 3) ? 2 : 1) * TILE_B + doff, Bh + bsrc);
            if (NT == 3) CP16(st + 3 * TILE_B + doff, Bl + bsrc);
        }
        CP_COMMIT();
    };

    float acc[2][8][4];
#pragma unroll
    for (int mi = 0; mi < 2; mi++)
#pragma unroll
        for (int j = 0; j < 8; j++)
#pragma unroll
            for (int q = 0; q < 4; q++) acc[mi][j][q] = 0.f;

    const int fr = lane & 15;
    const int fc = (lane >> 4) << 3;
    const uint32_t aoff = (uint32_t)(((wm * 32 + fr) * RS + fc) * 2);
    const uint32_t boff = (uint32_t)(((wn * 64 + fr) * RS + fc) * 2);

    if (NT == 1) load_chunk(0);

    for (int c = 0; c < 4; c++) {
        if (NT == 1) {
            if (c < 3) { load_chunk(c + 1); CP_WAIT1(); }
            else       { CP_WAIT0(); }
        } else {
            load_chunk(c);
            CP_WAIT0();
        }
        __syncthreads();

        const uint32_t st  = (NT == 1) ? sb + (uint32_t)((c & 1) * 2 * TILE_B) : sb;
        const uint32_t sAh = st;
        const uint32_t sAl = st + TILE_B;                       // NT3 only
        const uint32_t sBh = st + ((NT == 3) ? 2 : 1) * TILE_B;
        const uint32_t sBl = st + 3 * TILE_B;                   // NT3 only

#pragma unroll
        for (int ks = 0; ks < 4; ks++) {
            const uint32_t kadd = (uint32_t)(ks * 16 * 2);
            uint32_t ahf[2][4], alf[2][4], bhf[4][4], blf[4][4];
#pragma unroll
            for (int mi = 0; mi < 2; mi++) {
                const uint32_t ao = aoff + (uint32_t)(mi * 16 * RS * 2) + kadd;
                ldm_x4(ahf[mi], sAh + ao);
                if (NT == 3) ldm_x4(alf[mi], sAl + ao);
            }
#pragma unroll
            for (int jj = 0; jj < 4; jj++) {
                const uint32_t bo = boff + (uint32_t)(jj * 16 * RS * 2) + kadd;
                ldm_x4(bhf[jj], sBh + bo);
                if (NT == 3) ldm_x4(blf[jj], sBl + bo);
            }
#pragma unroll
            for (int mi = 0; mi < 2; mi++)
#pragma unroll
                for (int j = 0; j < 8; j++) {
                    const int jj = j >> 1, sel = j & 1;
                    const uint32_t b0h = bhf[jj][sel], b1h = bhf[jj][sel + 2];
                    if (NT == 3) {
                        const uint32_t b0l = blf[jj][sel], b1l = blf[jj][sel + 2];
                        mma_bf16(acc[mi][j], ahf[mi], b0h, b1h);
                        mma_bf16(acc[mi][j], ahf[mi], b0l, b1l);
                        mma_bf16(acc[mi][j], alf[mi], b0h, b1h);
                    } else {
                        mma_f16(acc[mi][j], ahf[mi], b0h, b1h);
                    }
                }
        }
        __syncthreads();
    }

    // ---- epilogue ----
    const int gcol0 = bn + wn * 64;
    const float* bp = bias1;
    int cb = 0;
    if (gcol0 >= nsplit) { bp = bias2; cb = nsplit; }

    const int rq = lane >> 2;
    const int cq = (lane & 3) * 2;

    if (outhalf) {
        // head-major fp16 store: [b][h][pos][32]
        __half* Ch = (__half*)Cout;
        int rr[4], bb[4], pp[4];
#pragma unroll
        for (int r = 0; r < 4; r++) {
            rr[r] = bm + wm * 32 + (r >> 1) * 16 + (r & 1) * 8 + rq;
            bb[r] = rr[r] / Ltot;
            pp[r] = rr[r] - bb[r] * Ltot;
        }
#pragma unroll
        for (int mi = 0; mi < 2; mi++) {
#pragma unroll
            for (int j = 0; j < 8; j++) {
                const int col = gcol0 + j * 8 + cq;
                const float2 bv = *(const float2*)(bp + (col - cb));
                const int h  = col >> 5;
                const int ch = col & 31;
#pragma unroll
                for (int half2i = 0; half2i < 2; half2i++) {
                    const int r = mi * 2 + half2i;
                    if (rr[r] < M) {
                        const size_t o =
                            ((size_t)(bb[r] * 8 + h) * Ltot + pp[r]) * 32 + ch;
                        *(__half2*)(Ch + o) = __floats2half2_rn(
                            acc[mi][j][half2i * 2 + 0] + bv.x,
                            acc[mi][j][half2i * 2 + 1] + bv.y);
                    }
                }
            }
        }
    } else {
        float* Cf = (float*)Cout;
#pragma unroll
        for (int mi = 0; mi < 2; mi++) {
#pragma unroll
            for (int j = 0; j < 8; j++) {
                const int col = gcol0 + j * 8 + cq;
                const float2 bv = *(const float2*)(bp + (col - cb));
                const int row0 = bm + wm * 32 + mi * 16 + rq;
                if (row0 < M)
                    *(float2*)(Cf + (size_t)row0 * ldc + col) =
                        make_float2(acc[mi][j][0] + bv.x, acc[mi][j][1] + bv.y);
                if (row0 + 8 < M)
                    *(float2*)(Cf + (size_t)(row0 + 8) * ldc + col) =
                        make_float2(acc[mi][j][2] + bv.x, acc[mi][j][3] + bv.y);
            }
        }
    }
}

// ---- sampler v5: head-major pair loads + half2-packed coefficient shuffles --
__global__ __launch_bounds__(256) void msda_sample_v5(
    const float* __restrict__ rp, const int* __restrict__ shapes, int M)
{
    __shared__ int s_w[4], s_h[4], s_start[4];
    __shared__ float s_fw[4], s_fh[4];
    __shared__ int s_L;
    if (threadIdx.x == 0) {
        int st = 0;
        for (int l = 0; l < 4; l++) {
            int hh = shapes[2 * l], ww = shapes[2 * l + 1];
            s_h[l] = hh; s_w[l] = ww; s_start[l] = st;
            s_fh[l] = (float)hh; s_fw[l] = (float)ww;
            st += hh * ww;
        }
        s_L = st;
    }
    __syncthreads();
    const int Ltot = s_L;

    const unsigned FULL = 0xffffffffu;
    const int lane = threadIdx.x & 31;
    const int warp = threadIdx.x >> 5;
    const int t = blockIdx.x * 4 + (warp >> 1);
    if (t >= M) return;
    const int h   = (warp & 1) * 4 + (lane >> 3);
    const int sub = lane & 7;
    const int b   = t / Ltot;

    // ---------- owner phase: points pt = sub*2, sub*2+1 ----------
    int      pi[2], pst[2];
    uint32_t pwa[2], pwb[2];          // half2-packed (c00,c10) / (c01,c11)
    float2 lg = *(const float2*)(g_offattn + (size_t)t * 384 + 256 + h * 16
                                 + sub * 2);
    float mx = fmaxf(lg.x, lg.y);
#pragma unroll
    for (int s = 4; s; s >>= 1) mx = fmaxf(mx, __shfl_xor_sync(FULL, mx, s));
    float e0 = expf(lg.x - mx), e1 = expf(lg.y - mx);
    float sm = e0 + e1;
#pragma unroll
    for (int s = 4; s; s >>= 1) sm += __shfl_xor_sync(FULL, sm, s);
    const float inv = 1.f / sm;

#pragma unroll
    for (int s = 0; s < 2; s++) {
        const int pt = sub * 2 + s;
        const int l  = pt >> 2;
        const float aw = (s ? e1 : e0) * inv;
        float2 off = *(const float2*)(g_offattn + (size_t)t * 384 + h * 32 + pt * 2);
        float2 ref = *(const float2*)(rp + (size_t)t * 8 + l * 2);
        const int w_ = s_w[l], h_ = s_h[l];
        const float x = (ref.x + off.x) * s_fw[l] - 0.5f;
        const float y = (ref.y + off.y) * s_fh[l] - 0.5f;
        const float x0f = floorf(x), y0f = floorf(y);
        const float fx = x - x0f, fy = y - y0f;
        const int x0 = (int)x0f, y0 = (int)y0f;
        const float m00 = ((x0 >= 0)     & (x0 < w_)     & (y0 >= 0)     & (y0 < h_))     ? 1.f : 0.f;
        const float m10 = ((x0 + 1 >= 0) & (x0 + 1 < w_) & (y0 >= 0)     & (y0 < h_))     ? 1.f : 0.f;
        const float m01 = ((x0 >= 0)     & (x0 < w_)     & (y0 + 1 >= 0) & (y0 + 1 < h_)) ? 1.f : 0.f;
        const float m11 = ((x0 + 1 >= 0) & (x0 + 1 < w_) & (y0 + 1 >= 0) & (y0 + 1 < h_)) ? 1.f : 0.f;
        const int xc0 = min(max(x0, 0), w_ - 1);
        const int xc1 = min(max(x0 + 1, 0), w_ - 1);
        const int yc0 = min(max(y0, 0), h_ - 1);
        const int yc1 = min(max(y0 + 1, 0), h_ - 1);
        pi[s]  = s_start[l] + yc0 * w_ + xc0;
        pst[s] = (xc1 - xc0) | ((yc1 - yc0) * w_ << 16);
        const float gx1 = fx, gx0 = 1.f - fx;
        const float gy1 = fy, gy0 = 1.f - fy;
        __half2 wa = __floats2half2_rn(gx0 * gy0 * m00 * aw,   // c00 (lo)
                                       gx1 * gy0 * m10 * aw);  // c10 (hi)
        __half2 wb = __floats2half2_rn(gx0 * gy1 * m01 * aw,   // c01 (lo)
                                       gx1 * gy1 * m11 * aw);  // c11 (hi)
        pwa[s] = *(uint32_t*)&wa;
        pwb[s] = *(uint32_t*)&wb;
    }

    // ---------- consumer: pair loads, 4 shuffles per point ----------
    const int hi4 = sub >> 2;          // which tap of the pair
    const int q4  = sub & 3;           // uint4 index within 64B tap
    const uint4* vb = (const uint4*)g_value_h
                    + ((size_t)(b * 8 + h) * Ltot) * 4 + q4;
    float a8[8];
#pragma unroll
    for (int k = 0; k < 8; k++) a8[k] = 0.f;

#pragma unroll
    for (int pt = 0; pt < 16; pt++) {
        const int src  = pt >> 1;
        const int slot = pt & 1;
        const int      i00 = slot ? __shfl_sync(FULL, pi[1],  src, 8) : __shfl_sync(FULL, pi[0],  src, 8);
        const int      st  = slot ? __shfl_sync(FULL, pst[1], src, 8) : __shfl_sync(FULL, pst[0], src, 8);
        const uint32_t wa  = slot ? __shfl_sync(FULL, pwa[1], src, 8) : __shfl_sync(FULL, pwa[0], src, 8);
        const uint32_t wb  = slot ? __shfl_sync(FULL, pwb[1], src, 8) : __shfl_sync(FULL, pwb[0], src, 8);
        const int cs = st & 0xffff;
        const int rs = st >> 16;
        const int addsel = hi4 ? cs : 0;
        const uint4 uA = vb[(size_t)(i00 + addsel) * 4];        // v00|v10 pair
        const uint4 uB = vb[(size_t)(i00 + rs + addsel) * 4];   // v01|v11 pair
        const __half2 ha = *(const __half2*)&wa;
        const __half2 hb = *(const __half2*)&wb;
        const float cA = hi4 ? __high2float(ha) : __low2float(ha);
        const float cB = hi4 ? __high2float(hb) : __low2float(hb);
#define ACC8(u, cc)                                                            \
        {                                                                      \
            float2 f0 = __half22float2(*(const __half2*)&(u).x);               \
            float2 f1 = __half22float2(*(const __half2*)&(u).y);               \
            float2 f2 = __half22float2(*(const __half2*)&(u).z);               \
            float2 f3 = __half22float2(*(const __half2*)&(u).w);               \
            a8[0] = fmaf(cc, f0.x, a8[0]); a8[1] = fmaf(cc, f0.y, a8[1]);      \
            a8[2] = fmaf(cc, f1.x, a8[2]); a8[3] = fmaf(cc, f1.y, a8[3]);      \
            a8[4] = fmaf(cc, f2.x, a8[4]); a8[5] = fmaf(cc, f2.y, a8[5]);      \
            a8[6] = fmaf(cc, f3.x, a8[6]); a8[7] = fmaf(cc, f3.y, a8[7]);      \
        }
        ACC8(uA, cA) ACC8(uB, cB)
#undef ACC8
    }

    // fold the two tap-halves (lanes j and j+4 hold same channels)
#pragma unroll
    for (int k = 0; k < 8; k++)
        a8[k] += __shfl_xor_sync(FULL, a8[k], 4);

    // store 8 ch per lane from lanes j<4 (query-major msda, feeds GEMM3)
    if (hi4 == 0) {
        __half2 o0 = __floats2half2_rn(a8[0], a8[1]);
        __half2 o1 = __floats2half2_rn(a8[2], a8[3]);
        __half2 o2 = __floats2half2_rn(a8[4], a8[5]);
        __half2 o3 = __floats2half2_rn(a8[6], a8[7]);
        uint4 u;
        u.x = *(uint32_t*)&o0; u.y = *(uint32_t*)&o1;
        u.z = *(uint32_t*)&o2; u.w = *(uint32_t*)&o3;
        *(uint4*)(g_m_h16 + (size_t)t * 256 + h * 32 + q4 * 8) = u;
    }
}

// ---------------------------------------------------------------------------
extern "C" void kernel_launch(void* const* d_in, const int* in_sizes, int n_in,
                              void* d_out, int out_size)
{
    const float* query   = (const float*)d_in[0];
    const float* rp      = (const float*)d_in[1];
    const float* flat    = (const float*)d_in[2];
    const int*   shapes  = (const int*)  d_in[3];
    const float* W_off   = (const float*)d_in[4];
    const float* b_off   = (const float*)d_in[5];
    const float* W_attn  = (const float*)d_in[6];
    const float* b_attn  = (const float*)d_in[7];
    const float* W_val   = (const float*)d_in[8];
    const float* b_val   = (const float*)d_in[9];
    const float* W_out   = (const float*)d_in[10];
    const float* b_out   = (const float*)d_in[11];
    float* out = (float*)d_out;

    const int M = in_sizes[0] / 256;
    const int Ltot = M / 8;            // B = 8

    void *pvh, *poa, *pf16, *pm16, *pqh, *pql, *pwh, *pwl, *pw16;
    cudaGetSymbolAddress(&pvh, g_value_h);
    cudaGetSymbolAddress(&poa, g_offattn);
    cudaGetSymbolAddress(&pf16, g_f_h16);
    cudaGetSymbolAddress(&pm16, g_m_h16);
    cudaGetSymbolAddress(&pqh, g_q_hi); cudaGetSymbolAddress(&pql, g_q_lo);
    cudaGetSymbolAddress(&pwh, g_wt_hi); cudaGetSymbolAddress(&pwl, g_wt_lo);
    cudaGetSymbolAddress(&pw16, g_wt_h16);

    cudaFuncSetAttribute(gemm_nt<3>, cudaFuncAttributeMaxDynamicSharedMemorySize,
                         SM_GEMM);
    cudaFuncSetAttribute(gemm_nt<1>, cudaFuncAttributeMaxDynamicSharedMemorySize,
                         SM_GEMM);

    const int mtiles = (M + 127) / 128;
    const int splitg = (int)(MAXROWS * 64 / 256);

    const __nv_bfloat16* wh  = (const __nv_bfloat16*)pwh;
    const __nv_bfloat16* wl  = (const __nv_bfloat16*)pwl;
    const __half*        w16 = (const __half*)pw16;

    wt_convert<<<896, 256>>>(W_val, W_off, W_attn, W_out);
    split_f16<<<splitg, 256>>>(flat, (__half*)pf16, M * 64);
    split_mat<<<splitg, 256>>>(query, (__nv_bfloat16*)pqh, (__nv_bfloat16*)pql, M * 64);

    // GEMM1: value projection, fp16 single-pass -> fp16 HEAD-MAJOR
    gemm_nt<1><<<dim3(2, mtiles), 256, SM_GEMM>>>(
        (const __nv_bfloat16*)pf16, nullptr,
        (const __nv_bfloat16*)w16, nullptr,
        b_val, b_val, 256, pvh, 256, M, 256, 1, Ltot);
    // GEMM2: fused offsets+attn, 3-term bf16 -> fp32
    gemm_nt<3><<<dim3(3, mtiles), 256, SM_GEMM>>>(
        (const __nv_bfloat16*)pqh, (const __nv_bfloat16*)pql,
        wh + 256 * 256, wl + 256 * 256,
        b_off, b_attn, 256, poa, 384, M, 384, 0, Ltot);

    msda_sample_v5<<<dim3((M + 3) / 4), 256>>>(rp, shapes, M);

    // GEMM3: output projection, fp16 single-pass -> fp32 (d_out)
    gemm_nt<1><<<dim3(2, mtiles), 256, SM_GEMM>>>(
        (const __nv_bfloat16*)pm16, nullptr,
        (const __nv_bfloat16*)(w16 + 256 * 256), nullptr,
        b_out, b_out, 256, out, 256, M, 256, 0, Ltot);
}

// round 15
// speedup vs baseline: 1.1214x; 1.0234x over previous
#include <cuda_runtime.h>
#include <cuda_fp16.h>
#include <cuda_bf16.h>
#include <cstdint>

// ---------------------------------------------------------------------------
// DeformableAttention (MSDA): B=8, C=256, H=8, d=32, Lv=4, P=4
//   wt_convert : transpose weights -> bf16 hi/lo [896,256] + fp16 [512,256]
//   split_mat  : query fp32 -> bf16 hi/lo ; split_f16: flat fp32 -> fp16
//   gemm_nt<3> : bf16 3-term-split GEMM (offsets/attn), 128x128 CTA, 2 CTA/SM
//   gemm_nt<1> : fp16 single-pass GEMM (value, output), 2-stage cp.async
//   msda_sample: v6 -- v4 (fp32 coeff shuffles) + owner-precomputed BYTE
//                offsets (kills 64-bit IMAD address chains in consumer)
// r15 vs r14: sampler coefficients back to fp32 (v5 regressed); byte-offset
//             addressing. GEMMs unchanged (r12 config = measured floor).
// ---------------------------------------------------------------------------

#define MAXROWS 106496ull  // >= B*Nq = 8*13294, padded to 128

__device__ __align__(16) __half         g_value_h[MAXROWS * 256];   // head-major
__device__ float                        g_offattn[MAXROWS * 384];
__device__ __align__(16) __half         g_f_h16[MAXROWS * 256];
__device__ __align__(16) __half         g_m_h16[MAXROWS * 256];
__device__ __align__(16) __nv_bfloat16  g_q_hi[MAXROWS * 256], g_q_lo[MAXROWS * 256];
__device__ __align__(16) __nv_bfloat16  g_wt_hi[896 * 256],    g_wt_lo[896 * 256];
__device__ __align__(16) __half         g_wt_h16[512 * 256];   // W_val^T, W_out^T

// ---- helpers ----------------------------------------------------------------
__device__ __forceinline__ uint32_t smem_u32(const void* p) {
    uint32_t a;
    asm("{ .reg .u64 t; cvta.to.shared.u64 t, %1; cvt.u32.u64 %0, t; }"
        : "=r"(a) : "l"(p));
    return a;
}
__device__ __forceinline__ void ldm_x4(uint32_t* r, uint32_t addr) {
    asm volatile("ldmatrix.sync.aligned.m8n8.x4.shared.b16 {%0,%1,%2,%3}, [%4];"
                 : "=r"(r[0]), "=r"(r[1]), "=r"(r[2]), "=r"(r[3]) : "r"(addr));
}
__device__ __forceinline__ void mma_bf16(float* d, const uint32_t* a,
                                         uint32_t b0, uint32_t b1) {
    asm volatile(
        "mma.sync.aligned.m16n8k16.row.col.f32.bf16.bf16.f32 "
        "{%0,%1,%2,%3}, {%4,%5,%6,%7}, {%8,%9}, {%0,%1,%2,%3};"
        : "+f"(d[0]), "+f"(d[1]), "+f"(d[2]), "+f"(d[3])
        : "r"(a[0]), "r"(a[1]), "r"(a[2]), "r"(a[3]), "r"(b0), "r"(b1));
}
__device__ __forceinline__ void mma_f16(float* d, const uint32_t* a,
                                        uint32_t b0, uint32_t b1) {
    asm volatile(
        "mma.sync.aligned.m16n8k16.row.col.f32.f16.f16.f32 "
        "{%0,%1,%2,%3}, {%4,%5,%6,%7}, {%8,%9}, {%0,%1,%2,%3};"
        : "+f"(d[0]), "+f"(d[1]), "+f"(d[2]), "+f"(d[3])
        : "r"(a[0]), "r"(a[1]), "r"(a[2]), "r"(a[3]), "r"(b0), "r"(b1));
}
#define CP16(dst, src)                                                        \
    asm volatile("cp.async.cg.shared.global [%0], [%1], 16;"                  \
                 :: "r"(dst), "l"(src) : "memory")
#define CP_COMMIT() asm volatile("cp.async.commit_group;" ::: "memory")
#define CP_WAIT1()  asm volatile("cp.async.wait_group 1;" ::: "memory")
#define CP_WAIT0()  asm volatile("cp.async.wait_group 0;" ::: "memory")

// ---- weight pre-transpose + split --------------------------------------------
__global__ void wt_convert(const float* __restrict__ Wv, const float* __restrict__ Wo,
                           const float* __restrict__ Wa, const float* __restrict__ Wu) {
    int idx = blockIdx.x * 256 + threadIdx.x;   // 896*256 total
    if (idx >= 896 * 256) return;
    int n = idx >> 8, k = idx & 255;
    float v;
    if      (n < 256) v = Wv[k * 256 + n];
    else if (n < 512) v = Wo[k * 256 + (n - 256)];
    else if (n < 640) v = Wa[k * 128 + (n - 512)];
    else              v = Wu[k * 256 + (n - 640)];
    __nv_bfloat16 hi = __float2bfloat16(v);
    __nv_bfloat16 lo = __float2bfloat16(v - __bfloat162float(hi));
    g_wt_hi[n * 256 + k] = hi;
    g_wt_lo[n * 256 + k] = lo;
    if (n < 256)       g_wt_h16[n * 256 + k]               = __float2half(v);
    else if (n >= 640) g_wt_h16[(n - 640 + 256) * 256 + k] = __float2half(v);
}

// ---- query split: fp32 [M,256] -> bf16 hi/lo, zero pad rows ------------------
__global__ __launch_bounds__(256) void split_mat(
    const float* __restrict__ src, __nv_bfloat16* __restrict__ hi,
    __nv_bfloat16* __restrict__ lo, int nquad)
{
    const int idx = blockIdx.x * 256 + threadIdx.x;
    if (idx >= (int)(MAXROWS * 64)) return;
    float4 v = make_float4(0.f, 0.f, 0.f, 0.f);
    if (idx < nquad) v = ((const float4*)src)[idx];
    __nv_bfloat16 h0 = __float2bfloat16(v.x), h1 = __float2bfloat16(v.y);
    __nv_bfloat16 h2 = __float2bfloat16(v.z), h3 = __float2bfloat16(v.w);
    __nv_bfloat162 ph0(h0, h1), ph1(h2, h3);
    __nv_bfloat162 pl0(__float2bfloat16(v.x - __bfloat162float(h0)),
                       __float2bfloat16(v.y - __bfloat162float(h1)));
    __nv_bfloat162 pl1(__float2bfloat16(v.z - __bfloat162float(h2)),
                       __float2bfloat16(v.w - __bfloat162float(h3)));
    uint2 uh, ul;
    uh.x = *(uint32_t*)&ph0; uh.y = *(uint32_t*)&ph1;
    ul.x = *(uint32_t*)&pl0; ul.y = *(uint32_t*)&pl1;
    *(uint2*)(hi + (size_t)idx * 4) = uh;
    *(uint2*)(lo + (size_t)idx * 4) = ul;
}

// ---- flat convert: fp32 -> fp16, zero pad rows -------------------------------
__global__ __launch_bounds__(256) void split_f16(
    const float* __restrict__ src, __half* __restrict__ dst, int nquad)
{
    const int idx = blockIdx.x * 256 + threadIdx.x;
    if (idx >= (int)(MAXROWS * 64)) return;
    float4 v = make_float4(0.f, 0.f, 0.f, 0.f);
    if (idx < nquad) v = ((const float4*)src)[idx];
    __half2 a = __floats2half2_rn(v.x, v.y);
    __half2 b = __floats2half2_rn(v.z, v.w);
    uint2 u;
    u.x = *(uint32_t*)&a; u.y = *(uint32_t*)&b;
    *(uint2*)(dst + (size_t)idx * 4) = u;
}

// ---- templated mma.sync GEMM (r12 config: CTA 128x128, 2 CTAs/SM) -----------
// NT==3: bf16 3-term split, single stage.  NT==1: fp16 single, 2-stage pipeline.
// C[M,N] = A[M,256] @ B^T + bias ; bias routed at col nsplit.
// outhalf==1: fp16 HEAD-MAJOR value store [b][h][pos][32] (needs Ltot).
#define RS 72
#define TILE_B (128 * RS * 2)          // 18432 B
#define SM_GEMM (4 * TILE_B)           // 73728 B

template <int NT>
__global__ __launch_bounds__(256, 2) void gemm_nt(
    const __nv_bfloat16* __restrict__ Ah, const __nv_bfloat16* __restrict__ Al,
    const __nv_bfloat16* __restrict__ Bh, const __nv_bfloat16* __restrict__ Bl,
    const float* __restrict__ bias1, const float* __restrict__ bias2,
    int nsplit, void* __restrict__ Cout, int ldc, int M, int N, int outhalf,
    int Ltot)
{
    extern __shared__ char smem[];
    const uint32_t sb = smem_u32(smem);
    const int tid  = threadIdx.x;
    const int lane = tid & 31;
    const int wid  = tid >> 5;
    const int wm   = wid & 3;
    const int wn   = wid >> 2;
    const int bm   = blockIdx.y * 128;
    const int bn   = blockIdx.x * 128;

    auto load_chunk = [&](int c) {
        const uint32_t st = (NT == 1) ? sb + (uint32_t)((c & 1) * 2 * TILE_B) : sb;
        const int kb = c * 64;
#pragma unroll
        for (int i = 0; i < 4; i++) {
            const int idx = tid + i * 256;
            const int row = idx >> 3, gk = idx & 7;
            const uint32_t doff = (uint32_t)((row * RS + gk * 8) * 2);
            const size_t asrc = (size_t)(bm + row) * 256 + kb + gk * 8;
            const size_t bsrc = (size_t)(bn + row) * 256 + kb + gk * 8;
            CP16(st + doff, Ah + asrc);
            if (NT == 3) CP16(st + TILE_B + doff, Al + asrc);
            CP16(st + ((NT == 3) ? 2 : 1) * TILE_B + doff, Bh + bsrc);
            if (NT == 3) CP16(st + 3 * TILE_B + doff, Bl + bsrc);
        }
        CP_COMMIT();
    };

    float acc[2][8][4];
#pragma unroll
    for (int mi = 0; mi < 2; mi++)
#pragma unroll
        for (int j = 0; j < 8; j++)
#pragma unroll
            for (int q = 0; q < 4; q++) acc[mi][j][q] = 0.f;

    const int fr = lane & 15;
    const int fc = (lane >> 4) << 3;
    const uint32_t aoff = (uint32_t)(((wm * 32 + fr) * RS + fc) * 2);
    const uint32_t boff = (uint32_t)(((wn * 64 + fr) * RS + fc) * 2);

    if (NT == 1) load_chunk(0);

    for (int c = 0; c < 4; c++) {
        if (NT == 1) {
            if (c < 3) { load_chunk(c + 1); CP_WAIT1(); }
            else       { CP_WAIT0(); }
        } else {
            load_chunk(c);
            CP_WAIT0();
        }
        __syncthreads();

        const uint32_t st  = (NT == 1) ? sb + (uint32_t)((c & 1) * 2 * TILE_B) : sb;
        const uint32_t sAh = st;
        const uint32_t sAl = st + TILE_B;                       // NT3 only
        const uint32_t sBh = st + ((NT == 3) ? 2 : 1) * TILE_B;
        const uint32_t sBl = st + 3 * TILE_B;                   // NT3 only

#pragma unroll
        for (int ks = 0; ks < 4; ks++) {
            const uint32_t kadd = (uint32_t)(ks * 16 * 2);
            uint32_t ahf[2][4], alf[2][4], bhf[4][4], blf[4][4];
#pragma unroll
            for (int mi = 0; mi < 2; mi++) {
                const uint32_t ao = aoff + (uint32_t)(mi * 16 * RS * 2) + kadd;
                ldm_x4(ahf[mi], sAh + ao);
                if (NT == 3) ldm_x4(alf[mi], sAl + ao);
            }
#pragma unroll
            for (int jj = 0; jj < 4; jj++) {
                const uint32_t bo = boff + (uint32_t)(jj * 16 * RS * 2) + kadd;
                ldm_x4(bhf[jj], sBh + bo);
                if (NT == 3) ldm_x4(blf[jj], sBl + bo);
            }
#pragma unroll
            for (int mi = 0; mi < 2; mi++)
#pragma unroll
                for (int j = 0; j < 8; j++) {
                    const int jj = j >> 1, sel = j & 1;
                    const uint32_t b0h = bhf[jj][sel], b1h = bhf[jj][sel + 2];
                    if (NT == 3) {
                        const uint32_t b0l = blf[jj][sel], b1l = blf[jj][sel + 2];
                        mma_bf16(acc[mi][j], ahf[mi], b0h, b1h);
                        mma_bf16(acc[mi][j], ahf[mi], b0l, b1l);
                        mma_bf16(acc[mi][j], alf[mi], b0h, b1h);
                    } else {
                        mma_f16(acc[mi][j], ahf[mi], b0h, b1h);
                    }
                }
        }
        __syncthreads();
    }

    // ---- epilogue ----
    const int gcol0 = bn + wn * 64;
    const float* bp = bias1;
    int cb = 0;
    if (gcol0 >= nsplit) { bp = bias2; cb = nsplit; }

    const int rq = lane >> 2;
    const int cq = (lane & 3) * 2;

    if (outhalf) {
        // head-major fp16 store: [b][h][pos][32]
        __half* Ch = (__half*)Cout;
        int rr[4], bb[4], pp[4];
#pragma unroll
        for (int r = 0; r < 4; r++) {
            rr[r] = bm + wm * 32 + (r >> 1) * 16 + (r & 1) * 8 + rq;
            bb[r] = rr[r] / Ltot;
            pp[r] = rr[r] - bb[r] * Ltot;
        }
#pragma unroll
        for (int mi = 0; mi < 2; mi++) {
#pragma unroll
            for (int j = 0; j < 8; j++) {
                const int col = gcol0 + j * 8 + cq;
                const float2 bv = *(const float2*)(bp + (col - cb));
                const int h  = col >> 5;
                const int ch = col & 31;
#pragma unroll
                for (int half2i = 0; half2i < 2; half2i++) {
                    const int r = mi * 2 + half2i;
                    if (rr[r] < M) {
                        const size_t o =
                            ((size_t)(bb[r] * 8 + h) * Ltot + pp[r]) * 32 + ch;
                        *(__half2*)(Ch + o) = __floats2half2_rn(
                            acc[mi][j][half2i * 2 + 0] + bv.x,
                            acc[mi][j][half2i * 2 + 1] + bv.y);
                    }
                }
            }
        }
    } else {
        float* Cf = (float*)Cout;
#pragma unroll
        for (int mi = 0; mi < 2; mi++) {
#pragma unroll
            for (int j = 0; j < 8; j++) {
                const int col = gcol0 + j * 8 + cq;
                const float2 bv = *(const float2*)(bp + (col - cb));
                const int row0 = bm + wm * 32 + mi * 16 + rq;
                if (row0 < M)
                    *(float2*)(Cf + (size_t)row0 * ldc + col) =
                        make_float2(acc[mi][j][0] + bv.x, acc[mi][j][1] + bv.y);
                if (row0 + 8 < M)
                    *(float2*)(Cf + (size_t)(row0 + 8) * ldc + col) =
                        make_float2(acc[mi][j][2] + bv.x, acc[mi][j][3] + bv.y);
            }
        }
    }
}

// ---- sampler v6: v4 + owner-precomputed byte offsets -------------------------
__global__ __launch_bounds__(256) void msda_sample_v6(
    const float* __restrict__ rp, const int* __restrict__ shapes, int M)
{
    __shared__ int s_w[4], s_h[4], s_start[4];
    __shared__ float s_fw[4], s_fh[4];
    __shared__ int s_L;
    if (threadIdx.x == 0) {
        int st = 0;
        for (int l = 0; l < 4; l++) {
            int hh = shapes[2 * l], ww = shapes[2 * l + 1];
            s_h[l] = hh; s_w[l] = ww; s_start[l] = st;
            s_fh[l] = (float)hh; s_fw[l] = (float)ww;
            st += hh * ww;
        }
        s_L = st;
    }
    __syncthreads();
    const int Ltot = s_L;

    const unsigned FULL = 0xffffffffu;
    const int lane = threadIdx.x & 31;
    const int warp = threadIdx.x >> 5;
    const int t = blockIdx.x * 4 + (warp >> 1);
    if (t >= M) return;
    const int h   = (warp & 1) * 4 + (lane >> 3);
    const int sub = lane & 7;
    const int b   = t / Ltot;

    // ---------- owner phase: points pt = sub*2, sub*2+1 ----------
    int   pi[2], pst[2];              // pi: BYTE offset; pst: cs_b | rs_b<<16
    float pc00[2], pc10[2], pc01[2], pc11[2];
    float2 lg = *(const float2*)(g_offattn + (size_t)t * 384 + 256 + h * 16
                                 + sub * 2);
    float mx = fmaxf(lg.x, lg.y);
#pragma unroll
    for (int s = 4; s; s >>= 1) mx = fmaxf(mx, __shfl_xor_sync(FULL, mx, s));
    float e0 = expf(lg.x - mx), e1 = expf(lg.y - mx);
    float sm = e0 + e1;
#pragma unroll
    for (int s = 4; s; s >>= 1) sm += __shfl_xor_sync(FULL, sm, s);
    const float inv = 1.f / sm;

#pragma unroll
    for (int s = 0; s < 2; s++) {
        const int pt = sub * 2 + s;
        const int l  = pt >> 2;
        const float aw = (s ? e1 : e0) * inv;
        float2 off = *(const float2*)(g_offattn + (size_t)t * 384 + h * 32 + pt * 2);
        float2 ref = *(const float2*)(rp + (size_t)t * 8 + l * 2);
        const int w_ = s_w[l], h_ = s_h[l];
        const float x = (ref.x + off.x) * s_fw[l] - 0.5f;
        const float y = (ref.y + off.y) * s_fh[l] - 0.5f;
        const float x0f = floorf(x), y0f = floorf(y);
        const float fx = x - x0f, fy = y - y0f;
        const int x0 = (int)x0f, y0 = (int)y0f;
        const float m00 = ((x0 >= 0)     & (x0 < w_)     & (y0 >= 0)     & (y0 < h_))     ? 1.f : 0.f;
        const float m10 = ((x0 + 1 >= 0) & (x0 + 1 < w_) & (y0 >= 0)     & (y0 < h_))     ? 1.f : 0.f;
        const float m01 = ((x0 >= 0)     & (x0 < w_)     & (y0 + 1 >= 0) & (y0 + 1 < h_)) ? 1.f : 0.f;
        const float m11 = ((x0 + 1 >= 0) & (x0 + 1 < w_) & (y0 + 1 >= 0) & (y0 + 1 < h_)) ? 1.f : 0.f;
        const int xc0 = min(max(x0, 0), w_ - 1);
        const int xc1 = min(max(x0 + 1, 0), w_ - 1);
        const int yc0 = min(max(y0, 0), h_ - 1);
        const int yc1 = min(max(y0 + 1, 0), h_ - 1);
        pi[s]  = (s_start[l] + yc0 * w_ + xc0) * 64;            // byte offset
        pst[s] = ((xc1 - xc0) * 64) | (((yc1 - yc0) * w_ * 64) << 16);
        const float gx1 = fx, gx0 = 1.f - fx;
        const float gy1 = fy, gy0 = 1.f - fy;
        pc00[s] = gx0 * gy0 * m00 * aw;
        pc10[s] = gx1 * gy0 * m10 * aw;
        pc01[s] = gx0 * gy1 * m01 * aw;
        pc11[s] = gx1 * gy1 * m11 * aw;
    }

    // ---------- consumer: pair loads, 32-bit byte-offset addressing ----------
    const int hi4 = sub >> 2;          // which tap of the pair
    const int q4  = sub & 3;           // uint4 index within 64B tap
    const char* vbase = (const char*)g_value_h
                      + ((size_t)(b * 8 + h) * Ltot) * 64 + q4 * 16;
    float a8[8];
#pragma unroll
    for (int k = 0; k < 8; k++) a8[k] = 0.f;

#pragma unroll
    for (int pt = 0; pt < 16; pt++) {
        const int src  = pt >> 1;
        const int slot = pt & 1;
        const int   i00 = slot ? __shfl_sync(FULL, pi[1],   src, 8) : __shfl_sync(FULL, pi[0],   src, 8);
        const int   st  = slot ? __shfl_sync(FULL, pst[1],  src, 8) : __shfl_sync(FULL, pst[0],  src, 8);
        const float c00 = slot ? __shfl_sync(FULL, pc00[1], src, 8) : __shfl_sync(FULL, pc00[0], src, 8);
        const float c10 = slot ? __shfl_sync(FULL, pc10[1], src, 8) : __shfl_sync(FULL, pc10[0], src, 8);
        const float c01 = slot ? __shfl_sync(FULL, pc01[1], src, 8) : __shfl_sync(FULL, pc01[0], src, 8);
        const float c11 = slot ? __shfl_sync(FULL, pc11[1], src, 8) : __shfl_sync(FULL, pc11[0], src, 8);
        const int cs_b = st & 0xffff;
        const int rs_b = st >> 16;
        const int offA = i00 + (hi4 ? cs_b : 0);
        const uint4 uA = *(const uint4*)(vbase + offA);         // v00|v10 pair
        const uint4 uB = *(const uint4*)(vbase + offA + rs_b);  // v01|v11 pair
        const float cA = hi4 ? c10 : c00;
        const float cB = hi4 ? c11 : c01;
#define ACC8(u, cc)                                                            \
        {                                                                      \
            float2 f0 = __half22float2(*(const __half2*)&(u).x);               \
            float2 f1 = __half22float2(*(const __half2*)&(u).y);               \
            float2 f2 = __half22float2(*(const __half2*)&(u).z);               \
            float2 f3 = __half22float2(*(const __half2*)&(u).w);               \
            a8[0] = fmaf(cc, f0.x, a8[0]); a8[1] = fmaf(cc, f0.y, a8[1]);      \
            a8[2] = fmaf(cc, f1.x, a8[2]); a8[3] = fmaf(cc, f1.y, a8[3]);      \
            a8[4] = fmaf(cc, f2.x, a8[4]); a8[5] = fmaf(cc, f2.y, a8[5]);      \
            a8[6] = fmaf(cc, f3.x, a8[6]); a8[7] = fmaf(cc, f3.y, a8[7]);      \
        }
        ACC8(uA, cA) ACC8(uB, cB)
#undef ACC8
    }

    // fold the two tap-halves (lanes j and j+4 hold same channels)
#pragma unroll
    for (int k = 0; k < 8; k++)
        a8[k] += __shfl_xor_sync(FULL, a8[k], 4);

    // store 8 ch per lane from lanes j<4 (query-major msda, feeds GEMM3)
    if (hi4 == 0) {
        __half2 o0 = __floats2half2_rn(a8[0], a8[1]);
        __half2 o1 = __floats2half2_rn(a8[2], a8[3]);
        __half2 o2 = __floats2half2_rn(a8[4], a8[5]);
        __half2 o3 = __floats2half2_rn(a8[6], a8[7]);
        uint4 u;
        u.x = *(uint32_t*)&o0; u.y = *(uint32_t*)&o1;
        u.z = *(uint32_t*)&o2; u.w = *(uint32_t*)&o3;
        *(uint4*)(g_m_h16 + (size_t)t * 256 + h * 32 + q4 * 8) = u;
    }
}

// ---------------------------------------------------------------------------
extern "C" void kernel_launch(void* const* d_in, const int* in_sizes, int n_in,
                              void* d_out, int out_size)
{
    const float* query   = (const float*)d_in[0];
    const float* rp      = (const float*)d_in[1];
    const float* flat    = (const float*)d_in[2];
    const int*   shapes  = (const int*)  d_in[3];
    const float* W_off   = (const float*)d_in[4];
    const float* b_off   = (const float*)d_in[5];
    const float* W_attn  = (const float*)d_in[6];
    const float* b_attn  = (const float*)d_in[7];
    const float* W_val   = (const float*)d_in[8];
    const float* b_val   = (const float*)d_in[9];
    const float* W_out   = (const float*)d_in[10];
    const float* b_out   = (const float*)d_in[11];
    float* out = (float*)d_out;

    const int M = in_sizes[0] / 256;
    const int Ltot = M / 8;            // B = 8

    void *pvh, *poa, *pf16, *pm16, *pqh, *pql, *pwh, *pwl, *pw16;
    cudaGetSymbolAddress(&pvh, g_value_h);
    cudaGetSymbolAddress(&poa, g_offattn);
    cudaGetSymbolAddress(&pf16, g_f_h16);
    cudaGetSymbolAddress(&pm16, g_m_h16);
    cudaGetSymbolAddress(&pqh, g_q_hi); cudaGetSymbolAddress(&pql, g_q_lo);
    cudaGetSymbolAddress(&pwh, g_wt_hi); cudaGetSymbolAddress(&pwl, g_wt_lo);
    cudaGetSymbolAddress(&pw16, g_wt_h16);

    cudaFuncSetAttribute(gemm_nt<3>, cudaFuncAttributeMaxDynamicSharedMemorySize,
                         SM_GEMM);
    cudaFuncSetAttribute(gemm_nt<1>, cudaFuncAttributeMaxDynamicSharedMemorySize,
                         SM_GEMM);

    const int mtiles = (M + 127) / 128;
    const int splitg = (int)(MAXROWS * 64 / 256);

    const __nv_bfloat16* wh  = (const __nv_bfloat16*)pwh;
    const __nv_bfloat16* wl  = (const __nv_bfloat16*)pwl;
    const __half*        w16 = (const __half*)pw16;

    wt_convert<<<896, 256>>>(W_val, W_off, W_attn, W_out);
    split_f16<<<splitg, 256>>>(flat, (__half*)pf16, M * 64);
    split_mat<<<splitg, 256>>>(query, (__nv_bfloat16*)pqh, (__nv_bfloat16*)pql, M * 64);

    // GEMM1: value projection, fp16 single-pass -> fp16 HEAD-MAJOR
    gemm_nt<1><<<dim3(2, mtiles), 256, SM_GEMM>>>(
        (const __nv_bfloat16*)pf16, nullptr,
        (const __nv_bfloat16*)w16, nullptr,
        b_val, b_val, 256, pvh, 256, M, 256, 1, Ltot);
    // GEMM2: fused offsets+attn, 3-term bf16 -> fp32
    gemm_nt<3><<<dim3(3, mtiles), 256, SM_GEMM>>>(
        (const __nv_bfloat16*)pqh, (const __nv_bfloat16*)pql,
        wh + 256 * 256, wl + 256 * 256,
        b_off, b_attn, 256, poa, 384, M, 384, 0, Ltot);

    msda_sample_v6<<<dim3((M + 3) / 4), 256>>>(rp, shapes, M);

    // GEMM3: output projection, fp16 single-pass -> fp32 (d_out)
    gemm_nt<1><<<dim3(2, mtiles), 256, SM_GEMM>>>(
        (const __nv_bfloat16*)pm16, nullptr,
        (const __nv_bfloat16*)(w16 + 256 * 256), nullptr,
        b_out, b_out, 256, out, 256, M, 256, 0, Ltot);
}

// round 16
// speedup vs baseline: 1.1294x; 1.0071x over previous
#include <cuda_runtime.h>
#include <cuda_fp16.h>
#include <cuda_bf16.h>
#include <cstdint>

// ---------------------------------------------------------------------------
// DeformableAttention (MSDA): B=8, C=256, H=8, d=32, Lv=4, P=4
//   wt_convert : transpose weights -> bf16 hi/lo [896,256] + fp16 [512,256]
//   split_mat  : query fp32 -> bf16 hi/lo ; split_f16: flat fp32 -> fp16
//   gemm_nt<3> : bf16 3-term-split GEMM (offsets/attn), 128x128 CTA, 2 CTA/SM
//   gemm_nt<1> : fp16 single-pass GEMM (value, output), 2-stage cp.async
//   msda_sample: v7 -- v6 + fp16 HFMA2 tap products (fp32 coeffs + fp32
//                cross-point accumulation preserved); cuts 32 cvt+fma ops
//                per point to ~26 issue slots.
// r16 vs r15: sampler consumer products in fp16 (HMUL2/HFMA2).
// ---------------------------------------------------------------------------

#define MAXROWS 106496ull  // >= B*Nq = 8*13294, padded to 128

__device__ __align__(16) __half         g_value_h[MAXROWS * 256];   // head-major
__device__ float                        g_offattn[MAXROWS * 384];
__device__ __align__(16) __half         g_f_h16[MAXROWS * 256];
__device__ __align__(16) __half         g_m_h16[MAXROWS * 256];
__device__ __align__(16) __nv_bfloat16  g_q_hi[MAXROWS * 256], g_q_lo[MAXROWS * 256];
__device__ __align__(16) __nv_bfloat16  g_wt_hi[896 * 256],    g_wt_lo[896 * 256];
__device__ __align__(16) __half         g_wt_h16[512 * 256];   // W_val^T, W_out^T

// ---- helpers ----------------------------------------------------------------
__device__ __forceinline__ uint32_t smem_u32(const void* p) {
    uint32_t a;
    asm("{ .reg .u64 t; cvta.to.shared.u64 t, %1; cvt.u32.u64 %0, t; }"
        : "=r"(a) : "l"(p));
    return a;
}
__device__ __forceinline__ void ldm_x4(uint32_t* r, uint32_t addr) {
    asm volatile("ldmatrix.sync.aligned.m8n8.x4.shared.b16 {%0,%1,%2,%3}, [%4];"
                 : "=r"(r[0]), "=r"(r[1]), "=r"(r[2]), "=r"(r[3]) : "r"(addr));
}
__device__ __forceinline__ void mma_bf16(float* d, const uint32_t* a,
                                         uint32_t b0, uint32_t b1) {
    asm volatile(
        "mma.sync.aligned.m16n8k16.row.col.f32.bf16.bf16.f32 "
        "{%0,%1,%2,%3}, {%4,%5,%6,%7}, {%8,%9}, {%0,%1,%2,%3};"
        : "+f"(d[0]), "+f"(d[1]), "+f"(d[2]), "+f"(d[3])
        : "r"(a[0]), "r"(a[1]), "r"(a[2]), "r"(a[3]), "r"(b0), "r"(b1));
}
__device__ __forceinline__ void mma_f16(float* d, const uint32_t* a,
                                        uint32_t b0, uint32_t b1) {
    asm volatile(
        "mma.sync.aligned.m16n8k16.row.col.f32.f16.f16.f32 "
        "{%0,%1,%2,%3}, {%4,%5,%6,%7}, {%8,%9}, {%0,%1,%2,%3};"
        : "+f"(d[0]), "+f"(d[1]), "+f"(d[2]), "+f"(d[3])
        : "r"(a[0]), "r"(a[1]), "r"(a[2]), "r"(a[3]), "r"(b0), "r"(b1));
}
#define CP16(dst, src)                                                        \
    asm volatile("cp.async.cg.shared.global [%0], [%1], 16;"                  \
                 :: "r"(dst), "l"(src) : "memory")
#define CP_COMMIT() asm volatile("cp.async.commit_group;" ::: "memory")
#define CP_WAIT1()  asm volatile("cp.async.wait_group 1;" ::: "memory")
#define CP_WAIT0()  asm volatile("cp.async.wait_group 0;" ::: "memory")

// ---- weight pre-transpose + split --------------------------------------------
__global__ void wt_convert(const float* __restrict__ Wv, const float* __restrict__ Wo,
                           const float* __restrict__ Wa, const float* __restrict__ Wu) {
    int idx = blockIdx.x * 256 + threadIdx.x;   // 896*256 total
    if (idx >= 896 * 256) return;
    int n = idx >> 8, k = idx & 255;
    float v;
    if      (n < 256) v = Wv[k * 256 + n];
    else if (n < 512) v = Wo[k * 256 + (n - 256)];
    else if (n < 640) v = Wa[k * 128 + (n - 512)];
    else              v = Wu[k * 256 + (n - 640)];
    __nv_bfloat16 hi = __float2bfloat16(v);
    __nv_bfloat16 lo = __float2bfloat16(v - __bfloat162float(hi));
    g_wt_hi[n * 256 + k] = hi;
    g_wt_lo[n * 256 + k] = lo;
    if (n < 256)       g_wt_h16[n * 256 + k]               = __float2half(v);
    else if (n >= 640) g_wt_h16[(n - 640 + 256) * 256 + k] = __float2half(v);
}

// ---- query split: fp32 [M,256] -> bf16 hi/lo, zero pad rows ------------------
__global__ __launch_bounds__(256) void split_mat(
    const float* __restrict__ src, __nv_bfloat16* __restrict__ hi,
    __nv_bfloat16* __restrict__ lo, int nquad)
{
    const int idx = blockIdx.x * 256 + threadIdx.x;
    if (idx >= (int)(MAXROWS * 64)) return;
    float4 v = make_float4(0.f, 0.f, 0.f, 0.f);
    if (idx < nquad) v = ((const float4*)src)[idx];
    __nv_bfloat16 h0 = __float2bfloat16(v.x), h1 = __float2bfloat16(v.y);
    __nv_bfloat16 h2 = __float2bfloat16(v.z), h3 = __float2bfloat16(v.w);
    __nv_bfloat162 ph0(h0, h1), ph1(h2, h3);
    __nv_bfloat162 pl0(__float2bfloat16(v.x - __bfloat162float(h0)),
                       __float2bfloat16(v.y - __bfloat162float(h1)));
    __nv_bfloat162 pl1(__float2bfloat16(v.z - __bfloat162float(h2)),
                       __float2bfloat16(v.w - __bfloat162float(h3)));
    uint2 uh, ul;
    uh.x = *(uint32_t*)&ph0; uh.y = *(uint32_t*)&ph1;
    ul.x = *(uint32_t*)&pl0; ul.y = *(uint32_t*)&pl1;
    *(uint2*)(hi + (size_t)idx * 4) = uh;
    *(uint2*)(lo + (size_t)idx * 4) = ul;
}

// ---- flat convert: fp32 -> fp16, zero pad rows -------------------------------
__global__ __launch_bounds__(256) void split_f16(
    const float* __restrict__ src, __half* __restrict__ dst, int nquad)
{
    const int idx = blockIdx.x * 256 + threadIdx.x;
    if (idx >= (int)(MAXROWS * 64)) return;
    float4 v = make_float4(0.f, 0.f, 0.f, 0.f);
    if (idx < nquad) v = ((const float4*)src)[idx];
    __half2 a = __floats2half2_rn(v.x, v.y);
    __half2 b = __floats2half2_rn(v.z, v.w);
    uint2 u;
    u.x = *(uint32_t*)&a; u.y = *(uint32_t*)&b;
    *(uint2*)(dst + (size_t)idx * 4) = u;
}

// ---- templated mma.sync GEMM (r12 config: CTA 128x128, 2 CTAs/SM) -----------
// NT==3: bf16 3-term split, single stage.  NT==1: fp16 single, 2-stage pipeline.
// C[M,N] = A[M,256] @ B^T + bias ; bias routed at col nsplit.
// outhalf==1: fp16 HEAD-MAJOR value store [b][h][pos][32] (needs Ltot).
#define RS 72
#define TILE_B (128 * RS * 2)          // 18432 B
#define SM_GEMM (4 * TILE_B)           // 73728 B

template <int NT>
__global__ __launch_bounds__(256, 2) void gemm_nt(
    const __nv_bfloat16* __restrict__ Ah, const __nv_bfloat16* __restrict__ Al,
    const __nv_bfloat16* __restrict__ Bh, const __nv_bfloat16* __restrict__ Bl,
    const float* __restrict__ bias1, const float* __restrict__ bias2,
    int nsplit, void* __restrict__ Cout, int ldc, int M, int N, int outhalf,
    int Ltot)
{
    extern __shared__ char smem[];
    const uint32_t sb = smem_u32(smem);
    const int tid  = threadIdx.x;
    const int lane = tid & 31;
    const int wid  = tid >> 5;
    const int wm   = wid & 3;
    const int wn   = wid >> 2;
    const int bm   = blockIdx.y * 128;
    const int bn   = blockIdx.x * 128;

    auto load_chunk = [&](int c) {
        const uint32_t st = (NT == 1) ? sb + (uint32_t)((c & 1) * 2 * TILE_B) : sb;
        const int kb = c * 64;
#pragma unroll
        for (int i = 0; i < 4; i++) {
            const int idx = tid + i * 256;
            const int row = idx >> 3, gk = idx & 7;
            const uint32_t doff = (uint32_t)((row * RS + gk * 8) * 2);
            const size_t asrc = (size_t)(bm + row) * 256 + kb + gk * 8;
            const size_t bsrc = (size_t)(bn + row) * 256 + kb + gk * 8;
            CP16(st + doff, Ah + asrc);
            if (NT == 3) CP16(st + TILE_B + doff, Al + asrc);
            CP16(st + ((NT == 3) ? 2 : 1) * TILE_B + doff, Bh + bsrc);
            if (NT == 3) CP16(st + 3 * TILE_B + doff, Bl + bsrc);
        }
        CP_COMMIT();
    };

    float acc[2][8][4];
#pragma unroll
    for (int mi = 0; mi < 2; mi++)
#pragma unroll
        for (int j = 0; j < 8; j++)
#pragma unroll
            for (int q = 0; q < 4; q++) acc[mi][j][q] = 0.f;

    const int fr = lane & 15;
    const int fc = (lane >> 4) << 3;
    const uint32_t aoff = (uint32_t)(((wm * 32 + fr) * RS + fc) * 2);
    const uint32_t boff = (uint32_t)(((wn * 64 + fr) * RS + fc) * 2);

    if (NT == 1) load_chunk(0);

    for (int c = 0; c < 4; c++) {
        if (NT == 1) {
            if (c < 3) { load_chunk(c + 1); CP_WAIT1(); }
            else       { CP_WAIT0(); }
        } else {
            load_chunk(c);
            CP_WAIT0();
        }
        __syncthreads();

        const uint32_t st  = (NT == 1) ? sb + (uint32_t)((c & 1) * 2 * TILE_B) : sb;
        const uint32_t sAh = st;
        const uint32_t sAl = st + TILE_B;                       // NT3 only
        const uint32_t sBh = st + ((NT == 3) ? 2 : 1) * TILE_B;
        const uint32_t sBl = st + 3 * TILE_B;                   // NT3 only

#pragma unroll
        for (int ks = 0; ks < 4; ks++) {
            const uint32_t kadd = (uint32_t)(ks * 16 * 2);
            uint32_t ahf[2][4], alf[2][4], bhf[4][4], blf[4][4];
#pragma unroll
            for (int mi = 0; mi < 2; mi++) {
                const uint32_t ao = aoff + (uint32_t)(mi * 16 * RS * 2) + kadd;
                ldm_x4(ahf[mi], sAh + ao);
                if (NT == 3) ldm_x4(alf[mi], sAl + ao);
            }
#pragma unroll
            for (int jj = 0; jj < 4; jj++) {
                const uint32_t bo = boff + (uint32_t)(jj * 16 * RS * 2) + kadd;
                ldm_x4(bhf[jj], sBh + bo);
                if (NT == 3) ldm_x4(blf[jj], sBl + bo);
            }
#pragma unroll
            for (int mi = 0; mi < 2; mi++)
#pragma unroll
                for (int j = 0; j < 8; j++) {
                    const int jj = j >> 1, sel = j & 1;
                    const uint32_t b0h = bhf[jj][sel], b1h = bhf[jj][sel + 2];
                    if (NT == 3) {
                        const uint32_t b0l = blf[jj][sel], b1l = blf[jj][sel + 2];
                        mma_bf16(acc[mi][j], ahf[mi], b0h, b1h);
                        mma_bf16(acc[mi][j], ahf[mi], b0l, b1l);
                        mma_bf16(acc[mi][j], alf[mi], b0h, b1h);
                    } else {
                        mma_f16(acc[mi][j], ahf[mi], b0h, b1h);
                    }
                }
        }
        __syncthreads();
    }

    // ---- epilogue ----
    const int gcol0 = bn + wn * 64;
    const float* bp = bias1;
    int cb = 0;
    if (gcol0 >= nsplit) { bp = bias2; cb = nsplit; }

    const int rq = lane >> 2;
    const int cq = (lane & 3) * 2;

    if (outhalf) {
        // head-major fp16 store: [b][h][pos][32]
        __half* Ch = (__half*)Cout;
        int rr[4], bb[4], pp[4];
#pragma unroll
        for (int r = 0; r < 4; r++) {
            rr[r] = bm + wm * 32 + (r >> 1) * 16 + (r & 1) * 8 + rq;
            bb[r] = rr[r] / Ltot;
            pp[r] = rr[r] - bb[r] * Ltot;
        }
#pragma unroll
        for (int mi = 0; mi < 2; mi++) {
#pragma unroll
            for (int j = 0; j < 8; j++) {
                const int col = gcol0 + j * 8 + cq;
                const float2 bv = *(const float2*)(bp + (col - cb));
                const int h  = col >> 5;
                const int ch = col & 31;
#pragma unroll
                for (int half2i = 0; half2i < 2; half2i++) {
                    const int r = mi * 2 + half2i;
                    if (rr[r] < M) {
                        const size_t o =
                            ((size_t)(bb[r] * 8 + h) * Ltot + pp[r]) * 32 + ch;
                        *(__half2*)(Ch + o) = __floats2half2_rn(
                            acc[mi][j][half2i * 2 + 0] + bv.x,
                            acc[mi][j][half2i * 2 + 1] + bv.y);
                    }
                }
            }
        }
    } else {
        float* Cf = (float*)Cout;
#pragma unroll
        for (int mi = 0; mi < 2; mi++) {
#pragma unroll
            for (int j = 0; j < 8; j++) {
                const int col = gcol0 + j * 8 + cq;
                const float2 bv = *(const float2*)(bp + (col - cb));
                const int row0 = bm + wm * 32 + mi * 16 + rq;
                if (row0 < M)
                    *(float2*)(Cf + (size_t)row0 * ldc + col) =
                        make_float2(acc[mi][j][0] + bv.x, acc[mi][j][1] + bv.y);
                if (row0 + 8 < M)
                    *(float2*)(Cf + (size_t)(row0 + 8) * ldc + col) =
                        make_float2(acc[mi][j][2] + bv.x, acc[mi][j][3] + bv.y);
            }
        }
    }
}

// ---- sampler v7: v6 + fp16 HFMA2 tap products --------------------------------
__global__ __launch_bounds__(256) void msda_sample_v7(
    const float* __restrict__ rp, const int* __restrict__ shapes, int M)
{
    __shared__ int s_w[4], s_h[4], s_start[4];
    __shared__ float s_fw[4], s_fh[4];
    __shared__ int s_L;
    if (threadIdx.x == 0) {
        int st = 0;
        for (int l = 0; l < 4; l++) {
            int hh = shapes[2 * l], ww = shapes[2 * l + 1];
            s_h[l] = hh; s_w[l] = ww; s_start[l] = st;
            s_fh[l] = (float)hh; s_fw[l] = (float)ww;
            st += hh * ww;
        }
        s_L = st;
    }
    __syncthreads();
    const int Ltot = s_L;

    const unsigned FULL = 0xffffffffu;
    const int lane = threadIdx.x & 31;
    const int warp = threadIdx.x >> 5;
    const int t = blockIdx.x * 4 + (warp >> 1);
    if (t >= M) return;
    const int h   = (warp & 1) * 4 + (lane >> 3);
    const int sub = lane & 7;
    const int b   = t / Ltot;

    // ---------- owner phase: points pt = sub*2, sub*2+1 ----------
    int   pi[2], pst[2];              // pi: BYTE offset; pst: cs_b | rs_b<<16
    float pc00[2], pc10[2], pc01[2], pc11[2];
    float2 lg = *(const float2*)(g_offattn + (size_t)t * 384 + 256 + h * 16
                                 + sub * 2);
    float mx = fmaxf(lg.x, lg.y);
#pragma unroll
    for (int s = 4; s; s >>= 1) mx = fmaxf(mx, __shfl_xor_sync(FULL, mx, s));
    float e0 = expf(lg.x - mx), e1 = expf(lg.y - mx);
    float sm = e0 + e1;
#pragma unroll
    for (int s = 4; s; s >>= 1) sm += __shfl_xor_sync(FULL, sm, s);
    const float inv = 1.f / sm;

#pragma unroll
    for (int s = 0; s < 2; s++) {
        const int pt = sub * 2 + s;
        const int l  = pt >> 2;
        const float aw = (s ? e1 : e0) * inv;
        float2 off = *(const float2*)(g_offattn + (size_t)t * 384 + h * 32 + pt * 2);
        float2 ref = *(const float2*)(rp + (size_t)t * 8 + l * 2);
        const int w_ = s_w[l], h_ = s_h[l];
        const float x = (ref.x + off.x) * s_fw[l] - 0.5f;
        const float y = (ref.y + off.y) * s_fh[l] - 0.5f;
        const float x0f = floorf(x), y0f = floorf(y);
        const float fx = x - x0f, fy = y - y0f;
        const int x0 = (int)x0f, y0 = (int)y0f;
        const float m00 = ((x0 >= 0)     & (x0 < w_)     & (y0 >= 0)     & (y0 < h_))     ? 1.f : 0.f;
        const float m10 = ((x0 + 1 >= 0) & (x0 + 1 < w_) & (y0 >= 0)     & (y0 < h_))     ? 1.f : 0.f;
        const float m01 = ((x0 >= 0)     & (x0 < w_)     & (y0 + 1 >= 0) & (y0 + 1 < h_)) ? 1.f : 0.f;
        const float m11 = ((x0 + 1 >= 0) & (x0 + 1 < w_) & (y0 + 1 >= 0) & (y0 + 1 < h_)) ? 1.f : 0.f;
        const int xc0 = min(max(x0, 0), w_ - 1);
        const int xc1 = min(max(x0 + 1, 0), w_ - 1);
        const int yc0 = min(max(y0, 0), h_ - 1);
        const int yc1 = min(max(y0 + 1, 0), h_ - 1);
        pi[s]  = (s_start[l] + yc0 * w_ + xc0) * 64;            // byte offset
        pst[s] = ((xc1 - xc0) * 64) | (((yc1 - yc0) * w_ * 64) << 16);
        const float gx1 = fx, gx0 = 1.f - fx;
        const float gy1 = fy, gy0 = 1.f - fy;
        pc00[s] = gx0 * gy0 * m00 * aw;
        pc10[s] = gx1 * gy0 * m10 * aw;
        pc01[s] = gx0 * gy1 * m01 * aw;
        pc11[s] = gx1 * gy1 * m11 * aw;
    }

    // ---------- consumer: pair loads, fp16 products, fp32 accumulation -------
    const int hi4 = sub >> 2;          // which tap of the pair
    const int q4  = sub & 3;           // uint4 index within 64B tap
    const char* vbase = (const char*)g_value_h
                      + ((size_t)(b * 8 + h) * Ltot) * 64 + q4 * 16;
    float a8[8];
#pragma unroll
    for (int k = 0; k < 8; k++) a8[k] = 0.f;

#pragma unroll
    for (int pt = 0; pt < 16; pt++) {
        const int src  = pt >> 1;
        const int slot = pt & 1;
        const int   i00 = slot ? __shfl_sync(FULL, pi[1],   src, 8) : __shfl_sync(FULL, pi[0],   src, 8);
        const int   st  = slot ? __shfl_sync(FULL, pst[1],  src, 8) : __shfl_sync(FULL, pst[0],  src, 8);
        const float c00 = slot ? __shfl_sync(FULL, pc00[1], src, 8) : __shfl_sync(FULL, pc00[0], src, 8);
        const float c10 = slot ? __shfl_sync(FULL, pc10[1], src, 8) : __shfl_sync(FULL, pc10[0], src, 8);
        const float c01 = slot ? __shfl_sync(FULL, pc01[1], src, 8) : __shfl_sync(FULL, pc01[0], src, 8);
        const float c11 = slot ? __shfl_sync(FULL, pc11[1], src, 8) : __shfl_sync(FULL, pc11[0], src, 8);
        const int cs_b = st & 0xffff;
        const int rs_b = st >> 16;
        const int offA = i00 + (hi4 ? cs_b : 0);
        const uint4 uA = *(const uint4*)(vbase + offA);         // v00|v10 pair
        const uint4 uB = *(const uint4*)(vbase + offA + rs_b);  // v01|v11 pair
        const __half2 cA2 = __float2half2_rn(hi4 ? c10 : c00);
        const __half2 cB2 = __float2half2_rn(hi4 ? c11 : c01);
        // t = vA*cA + vB*cB in fp16 (per-point products), accumulate in fp32
#pragma unroll
        for (int q = 0; q < 4; q++) {
            const __half2 vA = ((const __half2*)&uA)[q];
            const __half2 vB = ((const __half2*)&uB)[q];
            __half2 tq = __hmul2(vA, cA2);
            tq = __hfma2(vB, cB2, tq);
            const float2 f = __half22float2(tq);
            a8[q * 2 + 0] += f.x;
            a8[q * 2 + 1] += f.y;
        }
    }

    // fold the two tap-halves (lanes j and j+4 hold same channels)
#pragma unroll
    for (int k = 0; k < 8; k++)
        a8[k] += __shfl_xor_sync(FULL, a8[k], 4);

    // store 8 ch per lane from lanes j<4 (query-major msda, feeds GEMM3)
    if (hi4 == 0) {
        __half2 o0 = __floats2half2_rn(a8[0], a8[1]);
        __half2 o1 = __floats2half2_rn(a8[2], a8[3]);
        __half2 o2 = __floats2half2_rn(a8[4], a8[5]);
        __half2 o3 = __floats2half2_rn(a8[6], a8[7]);
        uint4 u;
        u.x = *(uint32_t*)&o0; u.y = *(uint32_t*)&o1;
        u.z = *(uint32_t*)&o2; u.w = *(uint32_t*)&o3;
        *(uint4*)(g_m_h16 + (size_t)t * 256 + h * 32 + q4 * 8) = u;
    }
}

// ---------------------------------------------------------------------------
extern "C" void kernel_launch(void* const* d_in, const int* in_sizes, int n_in,
                              void* d_out, int out_size)
{
    const float* query   = (const float*)d_in[0];
    const float* rp      = (const float*)d_in[1];
    const float* flat    = (const float*)d_in[2];
    const int*   shapes  = (const int*)  d_in[3];
    const float* W_off   = (const float*)d_in[4];
    const float* b_off   = (const float*)d_in[5];
    const float* W_attn  = (const float*)d_in[6];
    const float* b_attn  = (const float*)d_in[7];
    const float* W_val   = (const float*)d_in[8];
    const float* b_val   = (const float*)d_in[9];
    const float* W_out   = (const float*)d_in[10];
    const float* b_out   = (const float*)d_in[11];
    float* out = (float*)d_out;

    const int M = in_sizes[0] / 256;
    const int Ltot = M / 8;            // B = 8

    void *pvh, *poa, *pf16, *pm16, *pqh, *pql, *pwh, *pwl, *pw16;
    cudaGetSymbolAddress(&pvh, g_value_h);
    cudaGetSymbolAddress(&poa, g_offattn);
    cudaGetSymbolAddress(&pf16, g_f_h16);
    cudaGetSymbolAddress(&pm16, g_m_h16);
    cudaGetSymbolAddress(&pqh, g_q_hi); cudaGetSymbolAddress(&pql, g_q_lo);
    cudaGetSymbolAddress(&pwh, g_wt_hi); cudaGetSymbolAddress(&pwl, g_wt_lo);
    cudaGetSymbolAddress(&pw16, g_wt_h16);

    cudaFuncSetAttribute(gemm_nt<3>, cudaFuncAttributeMaxDynamicSharedMemorySize,
                         SM_GEMM);
    cudaFuncSetAttribute(gemm_nt<1>, cudaFuncAttributeMaxDynamicSharedMemorySize,
                         SM_GEMM);

    const int mtiles = (M + 127) / 128;
    const int splitg = (int)(MAXROWS * 64 / 256);

    const __nv_bfloat16* wh  = (const __nv_bfloat16*)pwh;
    const __nv_bfloat16* wl  = (const __nv_bfloat16*)pwl;
    const __half*        w16 = (const __half*)pw16;

    wt_convert<<<896, 256>>>(W_val, W_off, W_attn, W_out);
    split_f16<<<splitg, 256>>>(flat, (__half*)pf16, M * 64);
    split_mat<<<splitg, 256>>>(query, (__nv_bfloat16*)pqh, (__nv_bfloat16*)pql, M * 64);

    // GEMM1: value projection, fp16 single-pass -> fp16 HEAD-MAJOR
    gemm_nt<1><<<dim3(2, mtiles), 256, SM_GEMM>>>(
        (const __nv_bfloat16*)pf16, nullptr,
        (const __nv_bfloat16*)w16, nullptr,
        b_val, b_val, 256, pvh, 256, M, 256, 1, Ltot);
    // GEMM2: fused offsets+attn, 3-term bf16 -> fp32
    gemm_nt<3><<<dim3(3, mtiles), 256, SM_GEMM>>>(
        (const __nv_bfloat16*)pqh, (const __nv_bfloat16*)pql,
        wh + 256 * 256, wl + 256 * 256,
        b_off, b_attn, 256, poa, 384, M, 384, 0, Ltot);

    msda_sample_v7<<<dim3((M + 3) / 4), 256>>>(rp, shapes, M);

    // GEMM3: output projection, fp16 single-pass -> fp32 (d_out)
    gemm_nt<1><<<dim3(2, mtiles), 256, SM_GEMM>>>(
        (const __nv_bfloat16*)pm16, nullptr,
        (const __nv_bfloat16*)(w16 + 256 * 256), nullptr,
        b_out, b_out, 256, out, 256, M, 256, 0, Ltot);
}

// round 17
// speedup vs baseline: 1.1545x; 1.0222x over previous
#include <cuda_runtime.h>
#include <cuda_fp16.h>
#include <cuda_bf16.h>
#include <cstdint>

// ---------------------------------------------------------------------------
// DeformableAttention (MSDA): B=8, C=256, H=8, d=32, Lv=4, P=4
//   prep_all   : ONE launch = weight transpose/split + flat->fp16 + query->bf16x2
//   gemm_fused : ONE launch = GEMM1 (fp16 value proj, head-major out) +
//                GEMM2 (bf16 3-term off+attn) -- independent, tail-filling
//   msda_sample: v7 (head-major pair loads, HFMA2 products)
//   gemm_out   : GEMM3 fp16 single-pass -> d_out
// r17 vs r16: kernel fusion (6 launches -> 4); per-kernel configs unchanged.
// ---------------------------------------------------------------------------

#define MAXROWS 106496ull  // >= B*Nq = 8*13294, padded to 128
#define SPLITG  26624      // MAXROWS*64/256

__device__ __align__(16) __half         g_value_h[MAXROWS * 256];   // head-major
__device__ float                        g_offattn[MAXROWS * 384];
__device__ __align__(16) __half         g_f_h16[MAXROWS * 256];
__device__ __align__(16) __half         g_m_h16[MAXROWS * 256];
__device__ __align__(16) __nv_bfloat16  g_q_hi[MAXROWS * 256], g_q_lo[MAXROWS * 256];
__device__ __align__(16) __nv_bfloat16  g_wt_hi[896 * 256],    g_wt_lo[896 * 256];
__device__ __align__(16) __half         g_wt_h16[512 * 256];   // W_val^T, W_out^T

// ---- helpers ----------------------------------------------------------------
__device__ __forceinline__ uint32_t smem_u32(const void* p) {
    uint32_t a;
    asm("{ .reg .u64 t; cvta.to.shared.u64 t, %1; cvt.u32.u64 %0, t; }"
        : "=r"(a) : "l"(p));
    return a;
}
__device__ __forceinline__ void ldm_x4(uint32_t* r, uint32_t addr) {
    asm volatile("ldmatrix.sync.aligned.m8n8.x4.shared.b16 {%0,%1,%2,%3}, [%4];"
                 : "=r"(r[0]), "=r"(r[1]), "=r"(r[2]), "=r"(r[3]) : "r"(addr));
}
__device__ __forceinline__ void mma_bf16(float* d, const uint32_t* a,
                                         uint32_t b0, uint32_t b1) {
    asm volatile(
        "mma.sync.aligned.m16n8k16.row.col.f32.bf16.bf16.f32 "
        "{%0,%1,%2,%3}, {%4,%5,%6,%7}, {%8,%9}, {%0,%1,%2,%3};"
        : "+f"(d[0]), "+f"(d[1]), "+f"(d[2]), "+f"(d[3])
        : "r"(a[0]), "r"(a[1]), "r"(a[2]), "r"(a[3]), "r"(b0), "r"(b1));
}
__device__ __forceinline__ void mma_f16(float* d, const uint32_t* a,
                                        uint32_t b0, uint32_t b1) {
    asm volatile(
        "mma.sync.aligned.m16n8k16.row.col.f32.f16.f16.f32 "
        "{%0,%1,%2,%3}, {%4,%5,%6,%7}, {%8,%9}, {%0,%1,%2,%3};"
        : "+f"(d[0]), "+f"(d[1]), "+f"(d[2]), "+f"(d[3])
        : "r"(a[0]), "r"(a[1]), "r"(a[2]), "r"(a[3]), "r"(b0), "r"(b1));
}
#define CP16(dst, src)                                                        \
    asm volatile("cp.async.cg.shared.global [%0], [%1], 16;"                  \
                 :: "r"(dst), "l"(src) : "memory")
#define CP_COMMIT() asm volatile("cp.async.commit_group;" ::: "memory")
#define CP_WAIT1()  asm volatile("cp.async.wait_group 1;" ::: "memory")
#define CP_WAIT0()  asm volatile("cp.async.wait_group 0;" ::: "memory")

// ---- fused prep: weights + flat->fp16 + query->bf16 hi/lo -------------------
__global__ __launch_bounds__(256) void prep_all(
    const float* __restrict__ Wv, const float* __restrict__ Wo,
    const float* __restrict__ Wa, const float* __restrict__ Wu,
    const float* __restrict__ flat, const float* __restrict__ query,
    int nquad)
{
    const int bid = blockIdx.x;
    if (bid < 896) {
        // weight transpose + split
        const int idx = bid * 256 + threadIdx.x;
        const int n = idx >> 8, k = idx & 255;
        float v;
        if      (n < 256) v = Wv[k * 256 + n];
        else if (n < 512) v = Wo[k * 256 + (n - 256)];
        else if (n < 640) v = Wa[k * 128 + (n - 512)];
        else              v = Wu[k * 256 + (n - 640)];
        __nv_bfloat16 hi = __float2bfloat16(v);
        __nv_bfloat16 lo = __float2bfloat16(v - __bfloat162float(hi));
        g_wt_hi[n * 256 + k] = hi;
        g_wt_lo[n * 256 + k] = lo;
        if (n < 256)       g_wt_h16[n * 256 + k]               = __float2half(v);
        else if (n >= 640) g_wt_h16[(n - 640 + 256) * 256 + k] = __float2half(v);
    } else if (bid < 896 + SPLITG) {
        // flat -> fp16
        const int idx = (bid - 896) * 256 + threadIdx.x;
        float4 v = make_float4(0.f, 0.f, 0.f, 0.f);
        if (idx < nquad) v = ((const float4*)flat)[idx];
        __half2 a = __floats2half2_rn(v.x, v.y);
        __half2 b = __floats2half2_rn(v.z, v.w);
        uint2 u;
        u.x = *(uint32_t*)&a; u.y = *(uint32_t*)&b;
        *(uint2*)(g_f_h16 + (size_t)idx * 4) = u;
    } else {
        // query -> bf16 hi/lo
        const int idx = (bid - 896 - SPLITG) * 256 + threadIdx.x;
        float4 v = make_float4(0.f, 0.f, 0.f, 0.f);
        if (idx < nquad) v = ((const float4*)query)[idx];
        __nv_bfloat16 h0 = __float2bfloat16(v.x), h1 = __float2bfloat16(v.y);
        __nv_bfloat16 h2 = __float2bfloat16(v.z), h3 = __float2bfloat16(v.w);
        __nv_bfloat162 ph0(h0, h1), ph1(h2, h3);
        __nv_bfloat162 pl0(__float2bfloat16(v.x - __bfloat162float(h0)),
                           __float2bfloat16(v.y - __bfloat162float(h1)));
        __nv_bfloat162 pl1(__float2bfloat16(v.z - __bfloat162float(h2)),
                           __float2bfloat16(v.w - __bfloat162float(h3)));
        uint2 uh, ul;
        uh.x = *(uint32_t*)&ph0; uh.y = *(uint32_t*)&ph1;
        ul.x = *(uint32_t*)&pl0; ul.y = *(uint32_t*)&pl1;
        *(uint2*)(g_q_hi + (size_t)idx * 4) = uh;
        *(uint2*)(g_q_lo + (size_t)idx * 4) = ul;
    }
}

// ---- GEMM body (r12 config: CTA 128x128) -------------------------------------
// NT==3: bf16 3-term split, single stage.  NT==1: fp16 single, 2-stage pipeline.
#define RS 72
#define TILE_B (128 * RS * 2)          // 18432 B
#define SM_GEMM (4 * TILE_B)           // 73728 B

template <int NT>
__device__ __forceinline__ void gemm_body(
    const __nv_bfloat16* __restrict__ Ah, const __nv_bfloat16* __restrict__ Al,
    const __nv_bfloat16* __restrict__ Bh, const __nv_bfloat16* __restrict__ Bl,
    const float* __restrict__ bias1, const float* __restrict__ bias2,
    int nsplit, void* __restrict__ Cout, int ldc, int M, int N, int outhalf,
    int Ltot, int bx, int by)
{
    extern __shared__ char smem[];
    const uint32_t sb = smem_u32(smem);
    const int tid  = threadIdx.x;
    const int lane = tid & 31;
    const int wid  = tid >> 5;
    const int wm   = wid & 3;
    const int wn   = wid >> 2;
    const int bm   = by * 128;
    const int bn   = bx * 128;

    auto load_chunk = [&](int c) {
        const uint32_t st = (NT == 1) ? sb + (uint32_t)((c & 1) * 2 * TILE_B) : sb;
        const int kb = c * 64;
#pragma unroll
        for (int i = 0; i < 4; i++) {
            const int idx = tid + i * 256;
            const int row = idx >> 3, gk = idx & 7;
            const uint32_t doff = (uint32_t)((row * RS + gk * 8) * 2);
            const size_t asrc = (size_t)(bm + row) * 256 + kb + gk * 8;
            const size_t bsrc = (size_t)(bn + row) * 256 + kb + gk * 8;
            CP16(st + doff, Ah + asrc);
            if (NT == 3) CP16(st + TILE_B + doff, Al + asrc);
            CP16(st + ((NT == 3) ? 2 : 1) * TILE_B + doff, Bh + bsrc);
            if (NT == 3) CP16(st + 3 * TILE_B + doff, Bl + bsrc);
        }
        CP_COMMIT();
    };

    float acc[2][8][4];
#pragma unroll
    for (int mi = 0; mi < 2; mi++)
#pragma unroll
        for (int j = 0; j < 8; j++)
#pragma unroll
            for (int q = 0; q < 4; q++) acc[mi][j][q] = 0.f;

    const int fr = lane & 15;
    const int fc = (lane >> 4) << 3;
    const uint32_t aoff = (uint32_t)(((wm * 32 + fr) * RS + fc) * 2);
    const uint32_t boff = (uint32_t)(((wn * 64 + fr) * RS + fc) * 2);

    if (NT == 1) load_chunk(0);

    for (int c = 0; c < 4; c++) {
        if (NT == 1) {
            if (c < 3) { load_chunk(c + 1); CP_WAIT1(); }
            else       { CP_WAIT0(); }
        } else {
            load_chunk(c);
            CP_WAIT0();
        }
        __syncthreads();

        const uint32_t st  = (NT == 1) ? sb + (uint32_t)((c & 1) * 2 * TILE_B) : sb;
        const uint32_t sAh = st;
        const uint32_t sAl = st + TILE_B;                       // NT3 only
        const uint32_t sBh = st + ((NT == 3) ? 2 : 1) * TILE_B;
        const uint32_t sBl = st + 3 * TILE_B;                   // NT3 only

#pragma unroll
        for (int ks = 0; ks < 4; ks++) {
            const uint32_t kadd = (uint32_t)(ks * 16 * 2);
            uint32_t ahf[2][4], alf[2][4], bhf[4][4], blf[4][4];
#pragma unroll
            for (int mi = 0; mi < 2; mi++) {
                const uint32_t ao = aoff + (uint32_t)(mi * 16 * RS * 2) + kadd;
                ldm_x4(ahf[mi], sAh + ao);
                if (NT == 3) ldm_x4(alf[mi], sAl + ao);
            }
#pragma unroll
            for (int jj = 0; jj < 4; jj++) {
                const uint32_t bo = boff + (uint32_t)(jj * 16 * RS * 2) + kadd;
                ldm_x4(bhf[jj], sBh + bo);
                if (NT == 3) ldm_x4(blf[jj], sBl + bo);
            }
#pragma unroll
            for (int mi = 0; mi < 2; mi++)
#pragma unroll
                for (int j = 0; j < 8; j++) {
                    const int jj = j >> 1, sel = j & 1;
                    const uint32_t b0h = bhf[jj][sel], b1h = bhf[jj][sel + 2];
                    if (NT == 3) {
                        const uint32_t b0l = blf[jj][sel], b1l = blf[jj][sel + 2];
                        mma_bf16(acc[mi][j], ahf[mi], b0h, b1h);
                        mma_bf16(acc[mi][j], ahf[mi], b0l, b1l);
                        mma_bf16(acc[mi][j], alf[mi], b0h, b1h);
                    } else {
                        mma_f16(acc[mi][j], ahf[mi], b0h, b1h);
                    }
                }
        }
        __syncthreads();
    }

    // ---- epilogue ----
    const int gcol0 = bn + wn * 64;
    const float* bp = bias1;
    int cb = 0;
    if (gcol0 >= nsplit) { bp = bias2; cb = nsplit; }

    const int rq = lane >> 2;
    const int cq = (lane & 3) * 2;

    if (outhalf) {
        // head-major fp16 store: [b][h][pos][32]
        __half* Ch = (__half*)Cout;
        int rr[4], bb[4], pp[4];
#pragma unroll
        for (int r = 0; r < 4; r++) {
            rr[r] = bm + wm * 32 + (r >> 1) * 16 + (r & 1) * 8 + rq;
            bb[r] = rr[r] / Ltot;
            pp[r] = rr[r] - bb[r] * Ltot;
        }
#pragma unroll
        for (int mi = 0; mi < 2; mi++) {
#pragma unroll
            for (int j = 0; j < 8; j++) {
                const int col = gcol0 + j * 8 + cq;
                const float2 bv = *(const float2*)(bp + (col - cb));
                const int h  = col >> 5;
                const int ch = col & 31;
#pragma unroll
                for (int half2i = 0; half2i < 2; half2i++) {
                    const int r = mi * 2 + half2i;
                    if (rr[r] < M) {
                        const size_t o =
                            ((size_t)(bb[r] * 8 + h) * Ltot + pp[r]) * 32 + ch;
                        *(__half2*)(Ch + o) = __floats2half2_rn(
                            acc[mi][j][half2i * 2 + 0] + bv.x,
                            acc[mi][j][half2i * 2 + 1] + bv.y);
                    }
                }
            }
        }
    } else {
        float* Cf = (float*)Cout;
#pragma unroll
        for (int mi = 0; mi < 2; mi++) {
#pragma unroll
            for (int j = 0; j < 8; j++) {
                const int col = gcol0 + j * 8 + cq;
                const float2 bv = *(const float2*)(bp + (col - cb));
                const int row0 = bm + wm * 32 + mi * 16 + rq;
                if (row0 < M)
                    *(float2*)(Cf + (size_t)row0 * ldc + col) =
                        make_float2(acc[mi][j][0] + bv.x, acc[mi][j][1] + bv.y);
                if (row0 + 8 < M)
                    *(float2*)(Cf + (size_t)(row0 + 8) * ldc + col) =
                        make_float2(acc[mi][j][2] + bv.x, acc[mi][j][3] + bv.y);
            }
        }
    }
}

// ---- fused GEMM1 (value, NT1) + GEMM2 (off+attn, NT3) -----------------------
__global__ __launch_bounds__(256, 2) void gemm_fused(
    const __half* __restrict__ f16, const __half* __restrict__ wv16,
    const float* __restrict__ b_val, __half* __restrict__ vout,
    const __nv_bfloat16* __restrict__ qh, const __nv_bfloat16* __restrict__ ql,
    const __nv_bfloat16* __restrict__ wh, const __nv_bfloat16* __restrict__ wl,
    const float* __restrict__ b_off, const float* __restrict__ b_attn,
    float* __restrict__ oa, int M, int Ltot, int mt1)
{
    const int by = (int)blockIdx.y;
    if (by < mt1) {
        if (blockIdx.x < 2)
            gemm_body<1>((const __nv_bfloat16*)f16, nullptr,
                         (const __nv_bfloat16*)wv16, nullptr,
                         b_val, b_val, 256, vout, 256, M, 256, 1, Ltot,
                         blockIdx.x, by);
    } else {
        gemm_body<3>(qh, ql, wh, wl, b_off, b_attn, 256, oa, 384, M, 384, 0,
                     Ltot, blockIdx.x, by - mt1);
    }
}

// ---- GEMM3 (output projection, NT1) ------------------------------------------
__global__ __launch_bounds__(256, 2) void gemm_out(
    const __half* __restrict__ m16, const __half* __restrict__ wo16,
    const float* __restrict__ b_out, float* __restrict__ Cout, int M, int Ltot)
{
    gemm_body<1>((const __nv_bfloat16*)m16, nullptr,
                 (const __nv_bfloat16*)wo16, nullptr,
                 b_out, b_out, 256, Cout, 256, M, 256, 0, Ltot,
                 blockIdx.x, blockIdx.y);
}

// ---- sampler v7: head-major pair loads + HFMA2 products ----------------------
__global__ __launch_bounds__(256) void msda_sample_v7(
    const float* __restrict__ rp, const int* __restrict__ shapes, int M)
{
    __shared__ int s_w[4], s_h[4], s_start[4];
    __shared__ float s_fw[4], s_fh[4];
    __shared__ int s_L;
    if (threadIdx.x == 0) {
        int st = 0;
        for (int l = 0; l < 4; l++) {
            int hh = shapes[2 * l], ww = shapes[2 * l + 1];
            s_h[l] = hh; s_w[l] = ww; s_start[l] = st;
            s_fh[l] = (float)hh; s_fw[l] = (float)ww;
            st += hh * ww;
        }
        s_L = st;
    }
    __syncthreads();
    const int Ltot = s_L;

    const unsigned FULL = 0xffffffffu;
    const int lane = threadIdx.x & 31;
    const int warp = threadIdx.x >> 5;
    const int t = blockIdx.x * 4 + (warp >> 1);
    if (t >= M) return;
    const int h   = (warp & 1) * 4 + (lane >> 3);
    const int sub = lane & 7;
    const int b   = t / Ltot;

    // ---------- owner phase: points pt = sub*2, sub*2+1 ----------
    int   pi[2], pst[2];              // pi: BYTE offset; pst: cs_b | rs_b<<16
    float pc00[2], pc10[2], pc01[2], pc11[2];
    float2 lg = *(const float2*)(g_offattn + (size_t)t * 384 + 256 + h * 16
                                 + sub * 2);
    float mx = fmaxf(lg.x, lg.y);
#pragma unroll
    for (int s = 4; s; s >>= 1) mx = fmaxf(mx, __shfl_xor_sync(FULL, mx, s));
    float e0 = expf(lg.x - mx), e1 = expf(lg.y - mx);
    float sm = e0 + e1;
#pragma unroll
    for (int s = 4; s; s >>= 1) sm += __shfl_xor_sync(FULL, sm, s);
    const float inv = 1.f / sm;

#pragma unroll
    for (int s = 0; s < 2; s++) {
        const int pt = sub * 2 + s;
        const int l  = pt >> 2;
        const float aw = (s ? e1 : e0) * inv;
        float2 off = *(const float2*)(g_offattn + (size_t)t * 384 + h * 32 + pt * 2);
        float2 ref = *(const float2*)(rp + (size_t)t * 8 + l * 2);
        const int w_ = s_w[l], h_ = s_h[l];
        const float x = (ref.x + off.x) * s_fw[l] - 0.5f;
        const float y = (ref.y + off.y) * s_fh[l] - 0.5f;
        const float x0f = floorf(x), y0f = floorf(y);
        const float fx = x - x0f, fy = y - y0f;
        const int x0 = (int)x0f, y0 = (int)y0f;
        const float m00 = ((x0 >= 0)     & (x0 < w_)     & (y0 >= 0)     & (y0 < h_))     ? 1.f : 0.f;
        const float m10 = ((x0 + 1 >= 0) & (x0 + 1 < w_) & (y0 >= 0)     & (y0 < h_))     ? 1.f : 0.f;
        const float m01 = ((x0 >= 0)     & (x0 < w_)     & (y0 + 1 >= 0) & (y0 + 1 < h_)) ? 1.f : 0.f;
        const float m11 = ((x0 + 1 >= 0) & (x0 + 1 < w_) & (y0 + 1 >= 0) & (y0 + 1 < h_)) ? 1.f : 0.f;
        const int xc0 = min(max(x0, 0), w_ - 1);
        const int xc1 = min(max(x0 + 1, 0), w_ - 1);
        const int yc0 = min(max(y0, 0), h_ - 1);
        const int yc1 = min(max(y0 + 1, 0), h_ - 1);
        pi[s]  = (s_start[l] + yc0 * w_ + xc0) * 64;            // byte offset
        pst[s] = ((xc1 - xc0) * 64) | (((yc1 - yc0) * w_ * 64) << 16);
        const float gx1 = fx, gx0 = 1.f - fx;
        const float gy1 = fy, gy0 = 1.f - fy;
        pc00[s] = gx0 * gy0 * m00 * aw;
        pc10[s] = gx1 * gy0 * m10 * aw;
        pc01[s] = gx0 * gy1 * m01 * aw;
        pc11[s] = gx1 * gy1 * m11 * aw;
    }

    // ---------- consumer: pair loads, fp16 products, fp32 accumulation -------
    const int hi4 = sub >> 2;          // which tap of the pair
    const int q4  = sub & 3;           // uint4 index within 64B tap
    const char* vbase = (const char*)g_value_h
                      + ((size_t)(b * 8 + h) * Ltot) * 64 + q4 * 16;
    float a8[8];
#pragma unroll
    for (int k = 0; k < 8; k++) a8[k] = 0.f;

#pragma unroll
    for (int pt = 0; pt < 16; pt++) {
        const int src  = pt >> 1;
        const int slot = pt & 1;
        const int   i00 = slot ? __shfl_sync(FULL, pi[1],   src, 8) : __shfl_sync(FULL, pi[0],   src, 8);
        const int   st  = slot ? __shfl_sync(FULL, pst[1],  src, 8) : __shfl_sync(FULL, pst[0],  src, 8);
        const float c00 = slot ? __shfl_sync(FULL, pc00[1], src, 8) : __shfl_sync(FULL, pc00[0], src, 8);
        const float c10 = slot ? __shfl_sync(FULL, pc10[1], src, 8) : __shfl_sync(FULL, pc10[0], src, 8);
        const float c01 = slot ? __shfl_sync(FULL, pc01[1], src, 8) : __shfl_sync(FULL, pc01[0], src, 8);
        const float c11 = slot ? __shfl_sync(FULL, pc11[1], src, 8) : __shfl_sync(FULL, pc11[0], src, 8);
        const int cs_b = st & 0xffff;
        const int rs_b = st >> 16;
        const int offA = i00 + (hi4 ? cs_b : 0);
        const uint4 uA = *(const uint4*)(vbase + offA);         // v00|v10 pair
        const uint4 uB = *(const uint4*)(vbase + offA + rs_b);  // v01|v11 pair
        const __half2 cA2 = __float2half2_rn(hi4 ? c10 : c00);
        const __half2 cB2 = __float2half2_rn(hi4 ? c11 : c01);
#pragma unroll
        for (int q = 0; q < 4; q++) {
            const __half2 vA = ((const __half2*)&uA)[q];
            const __half2 vB = ((const __half2*)&uB)[q];
            __half2 tq = __hmul2(vA, cA2);
            tq = __hfma2(vB, cB2, tq);
            const float2 f = __half22float2(tq);
            a8[q * 2 + 0] += f.x;
            a8[q * 2 + 1] += f.y;
        }
    }

    // fold the two tap-halves (lanes j and j+4 hold same channels)
#pragma unroll
    for (int k = 0; k < 8; k++)
        a8[k] += __shfl_xor_sync(FULL, a8[k], 4);

    // store 8 ch per lane from lanes j<4 (query-major msda, feeds GEMM3)
    if (hi4 == 0) {
        __half2 o0 = __floats2half2_rn(a8[0], a8[1]);
        __half2 o1 = __floats2half2_rn(a8[2], a8[3]);
        __half2 o2 = __floats2half2_rn(a8[4], a8[5]);
        __half2 o3 = __floats2half2_rn(a8[6], a8[7]);
        uint4 u;
        u.x = *(uint32_t*)&o0; u.y = *(uint32_t*)&o1;
        u.z = *(uint32_t*)&o2; u.w = *(uint32_t*)&o3;
        *(uint4*)(g_m_h16 + (size_t)t * 256 + h * 32 + q4 * 8) = u;
    }
}

// ---------------------------------------------------------------------------
extern "C" void kernel_launch(void* const* d_in, const int* in_sizes, int n_in,
                              void* d_out, int out_size)
{
    const float* query   = (const float*)d_in[0];
    const float* rp      = (const float*)d_in[1];
    const float* flat    = (const float*)d_in[2];
    const int*   shapes  = (const int*)  d_in[3];
    const float* W_off   = (const float*)d_in[4];
    const float* b_off   = (const float*)d_in[5];
    const float* W_attn  = (const float*)d_in[6];
    const float* b_attn  = (const float*)d_in[7];
    const float* W_val   = (const float*)d_in[8];
    const float* b_val   = (const float*)d_in[9];
    const float* W_out   = (const float*)d_in[10];
    const float* b_out   = (const float*)d_in[11];
    float* out = (float*)d_out;

    const int M = in_sizes[0] / 256;
    const int Ltot = M / 8;            // B = 8

    void *pvh, *poa, *pf16, *pm16, *pqh, *pql, *pwh, *pwl, *pw16;
    cudaGetSymbolAddress(&pvh, g_value_h);
    cudaGetSymbolAddress(&poa, g_offattn);
    cudaGetSymbolAddress(&pf16, g_f_h16);
    cudaGetSymbolAddress(&pm16, g_m_h16);
    cudaGetSymbolAddress(&pqh, g_q_hi); cudaGetSymbolAddress(&pql, g_q_lo);
    cudaGetSymbolAddress(&pwh, g_wt_hi); cudaGetSymbolAddress(&pwl, g_wt_lo);
    cudaGetSymbolAddress(&pw16, g_wt_h16);

    cudaFuncSetAttribute(gemm_fused, cudaFuncAttributeMaxDynamicSharedMemorySize,
                         SM_GEMM);
    cudaFuncSetAttribute(gemm_out, cudaFuncAttributeMaxDynamicSharedMemorySize,
                         SM_GEMM);

    const int mtiles = (M + 127) / 128;

    const __nv_bfloat16* wh  = (const __nv_bfloat16*)pwh;
    const __nv_bfloat16* wl  = (const __nv_bfloat16*)pwl;
    const __half*        w16 = (const __half*)pw16;

    // 1: fused prep (weights + both activation conversions)
    prep_all<<<896 + 2 * SPLITG, 256>>>(W_val, W_off, W_attn, W_out,
                                        flat, query, M * 64);

    // 2: fused GEMM1 (value, rows [0,mtiles)) + GEMM2 (off+attn, rows >= mtiles)
    gemm_fused<<<dim3(3, 2 * mtiles), 256, SM_GEMM>>>(
        (const __half*)pf16, w16, b_val, (__half*)pvh,
        (const __nv_bfloat16*)pqh, (const __nv_bfloat16*)pql,
        wh + 256 * 256, wl + 256 * 256, b_off, b_attn,
        (float*)poa, M, Ltot, mtiles);

    // 3: sampler
    msda_sample_v7<<<dim3((M + 3) / 4), 256>>>(rp, shapes, M);

    // 4: GEMM3 output projection
    gemm_out<<<dim3(2, mtiles), 256, SM_GEMM>>>(
        (const __half*)pm16, w16 + 256 * 256, b_out, out, M, Ltot);
}